// round 1
// baseline (speedup 1.0000x reference)
#include <cuda_runtime.h>
#include <math.h>

#define N_NODES 10000
#define N_EDGES 320000
#define N_GRAPHS 64

// ----------------------------- device scratch -------------------------------
__device__ float g_h1[N_NODES * 128];      // stage-1 hidden
__device__ float g_h2[N_NODES * 256];      // stage-2 hidden
__device__ float g_m [N_NODES * 256];      // linear output (pre-scatter)
__device__ float g_a [N_NODES * 256];      // aggregated messages
__device__ float g_gi[N_NODES * 768];      // GRU input gates
__device__ float g_gh[N_NODES * 768];      // GRU hidden gates
__device__ int   g_rowptr[N_NODES + 1];
__device__ int   g_cnt[N_NODES];
__device__ int   g_cursor[N_NODES];
__device__ int   g_csr_src[N_EDGES];
__device__ unsigned g_pool[N_GRAPHS * 256];
__device__ int   g_e64;                    // 1 if edge_index dtype is int64
__device__ int   g_b64;                    // 1 if batch dtype is int64

// ----------------------------- dtype detection ------------------------------
// jnp.int64 canonicalizes to int32 unless x64 enabled. All index values are
// < 10000 and non-negative, so for int64 every odd 32-bit word is zero.
// For int32, odd words are other (mostly nonzero) indices. Sample strided.
__global__ void detect_kernel(const void* edge, const void* batch) {
    if (threadIdx.x != 0 || blockIdx.x != 0) return;
    const unsigned* we = (const unsigned*)edge;
    int e64 = 1;
    for (int k = 0; k < 512; k++) {
        long i = (long)k * ((2L * N_EDGES) / 512);   // element index in [0, 2*NE)
        if (we[2 * i + 1] != 0u) { e64 = 0; break; }
    }
    g_e64 = e64;
    const unsigned* wb = (const unsigned*)batch;
    int b64 = 1;
    for (int k = 0; k < 512; k++) {
        long i = (long)k * (N_NODES / 512);
        if (i >= N_NODES) i = N_NODES - 1;
        if (wb[2 * i + 1] != 0u) { b64 = 0; break; }
    }
    g_b64 = b64;
}

__device__ __forceinline__ int load_idx(const void* p, long i, int is64) {
    return is64 ? (int)((const long long*)p)[i] : ((const int*)p)[i];
}

// ----------------------------- CSR build ------------------------------------
__global__ void zero_int_kernel(int* p, int n) {
    int i = blockIdx.x * blockDim.x + threadIdx.x;
    if (i < n) p[i] = 0;
}

__global__ void count_kernel(const void* edge, int* cnt) {
    int e = blockIdx.x * blockDim.x + threadIdx.x;
    if (e >= N_EDGES) return;
    int dst = load_idx(edge, (long)N_EDGES + e, g_e64);
    atomicAdd(&cnt[dst], 1);
}

// single-block exclusive scan (n=10000, blockDim=1024)
__global__ void scan_kernel(const int* cnt, int* rowptr, int n) {
    __shared__ int wsum[32];
    __shared__ int carry;
    int lane = threadIdx.x & 31, wid = threadIdx.x >> 5;
    if (threadIdx.x == 0) { carry = 0; rowptr[0] = 0; }
    __syncthreads();
    for (int base = 0; base < n; base += blockDim.x) {
        int i = base + threadIdx.x;
        int v = (i < n) ? cnt[i] : 0;
        int xv = v;
        #pragma unroll
        for (int o = 1; o < 32; o <<= 1) {
            int y = __shfl_up_sync(0xffffffffu, xv, o);
            if (lane >= o) xv += y;
        }
        if (lane == 31) wsum[wid] = xv;
        __syncthreads();
        if (wid == 0) {
            int s = wsum[lane];
            #pragma unroll
            for (int o = 1; o < 32; o <<= 1) {
                int y = __shfl_up_sync(0xffffffffu, s, o);
                if (lane >= o) s += y;
            }
            wsum[lane] = s;
        }
        __syncthreads();
        int incl = xv + (wid ? wsum[wid - 1] : 0) + carry;
        if (i < n) rowptr[i + 1] = incl;
        __syncthreads();
        if (threadIdx.x == blockDim.x - 1) carry = incl;
        __syncthreads();
    }
}

__global__ void copy_int_kernel(const int* src, int* dst, int n) {
    int i = blockIdx.x * blockDim.x + threadIdx.x;
    if (i < n) dst[i] = src[i];
}

__global__ void fill_kernel(const void* edge, int* cursor, int* csr_src) {
    int e = blockIdx.x * blockDim.x + threadIdx.x;
    if (e >= N_EDGES) return;
    int is64 = g_e64;
    int src = load_idx(edge, e, is64);
    int dst = load_idx(edge, (long)N_EDGES + e, is64);
    int pos = atomicAdd(&cursor[dst], 1);
    csr_src[pos] = src;
}

// ----------------------------- SGEMM (fp32) ---------------------------------
// C[N,M] = A[N,K] @ op(B) (+bias).  transB=0: B is [K,M]. transB=1: B is [M,K].
// BM=BN=64, BK=16, 256 threads, 4x4 micro-tile. M,K multiples of 64/16; only
// N needs guards (N=10000).
#define BM 64
#define BN 64
#define BK 16
__global__ __launch_bounds__(256) void gemm_kernel(
    const float* __restrict__ A, const float* __restrict__ B,
    const float* __restrict__ bias, float* __restrict__ C,
    int N, int K, int M, int transB)
{
    __shared__ float As[BK][BM + 4];
    __shared__ float Bs[BK][BN + 4];
    int tid = threadIdx.x;
    int tx = tid & 15, ty = tid >> 4;
    int row0 = blockIdx.y * BM;
    int col0 = blockIdx.x * BN;

    float acc[4][4];
    #pragma unroll
    for (int i = 0; i < 4; i++)
        #pragma unroll
        for (int j = 0; j < 4; j++) acc[i][j] = 0.f;

    for (int k0 = 0; k0 < K; k0 += BK) {
        #pragma unroll
        for (int i = 0; i < 4; i++) {
            int idx = tid + i * 256;           // 0..1023
            int m = idx >> 4;                  // 0..63
            int k = idx & 15;
            int gr = row0 + m;
            As[k][m] = (gr < N) ? A[(long)gr * K + k0 + k] : 0.f;
        }
        if (!transB) {
            #pragma unroll
            for (int i = 0; i < 4; i++) {
                int idx = tid + i * 256;
                int k = idx >> 6;              // 0..15
                int n = idx & 63;
                Bs[k][n] = B[(long)(k0 + k) * M + col0 + n];
            }
        } else {
            #pragma unroll
            for (int i = 0; i < 4; i++) {
                int idx = tid + i * 256;
                int n = idx >> 4;              // 0..63
                int k = idx & 15;
                Bs[k][n] = B[(long)(col0 + n) * K + k0 + k];
            }
        }
        __syncthreads();
        #pragma unroll
        for (int k = 0; k < BK; k++) {
            float ar[4], br[4];
            #pragma unroll
            for (int i = 0; i < 4; i++) ar[i] = As[k][ty * 4 + i];
            #pragma unroll
            for (int j = 0; j < 4; j++) br[j] = Bs[k][tx * 4 + j];
            #pragma unroll
            for (int i = 0; i < 4; i++)
                #pragma unroll
                for (int j = 0; j < 4; j++) acc[i][j] += ar[i] * br[j];
        }
        __syncthreads();
    }

    #pragma unroll
    for (int i = 0; i < 4; i++) {
        int gr = row0 + ty * 4 + i;
        if (gr >= N) continue;
        #pragma unroll
        for (int j = 0; j < 4; j++) {
            int gc = col0 + tx * 4 + j;
            float v = acc[i][j];
            if (bias) v += bias[gc];
            C[(long)gr * M + gc] = v;
        }
    }
}

// ----------------------------- edge aggregation -----------------------------
// a[n,:] = sum over incoming edges (CSR) of m[src,:]. Block per node, thread
// per feature. Reads are L2-resident (m is 10MB), writes coalesced, no atomics.
__global__ void aggregate_kernel(const float* __restrict__ m, float* __restrict__ a,
                                 const int* __restrict__ rowptr,
                                 const int* __restrict__ csr_src, int C)
{
    int n = blockIdx.x;
    int f = threadIdx.x;
    int beg = rowptr[n], end = rowptr[n + 1];
    float acc = 0.f;
    for (int j = beg; j < end; j++) {
        int s = csr_src[j];
        acc += m[(long)s * C + f];
    }
    a[(long)n * C + f] = acc;
}

// ----------------------------- GRU elementwise ------------------------------
__global__ void gru_kernel(const float* __restrict__ gi, const float* __restrict__ gh,
                           const float* __restrict__ h, float* __restrict__ hout, int C)
{
    int i = blockIdx.x * blockDim.x + threadIdx.x;
    int total = N_NODES * C;
    if (i >= total) return;
    int n = i / C, f = i % C;
    const float* gir = gi + (long)n * 3 * C;
    const float* ghr = gh + (long)n * 3 * C;
    float ir = gir[f], iz = gir[C + f], in_ = gir[2 * C + f];
    float hr = ghr[f], hz = ghr[C + f], hn  = ghr[2 * C + f];
    float r = 1.f / (1.f + expf(-(ir + hr)));
    float z = 1.f / (1.f + expf(-(iz + hz)));
    float nn = tanhf(in_ + r * hn);
    float hv = h[i];
    hout[i] = (1.f - z) * nn + z * hv;
}

// relu on stage-1 output and zero-pad 128 -> 256
__global__ void pad_relu_kernel(const float* __restrict__ h1, float* __restrict__ h2) {
    int i = blockIdx.x * blockDim.x + threadIdx.x;
    if (i >= N_NODES * 256) return;
    int n = i >> 8, f = i & 255;
    float v = (f < 128) ? fmaxf(h1[n * 128 + f], 0.f) : 0.f;
    h2[i] = v;
}

// ----------------------------- pooling + FC ---------------------------------
__device__ __forceinline__ unsigned f2ord(float f) {
    unsigned u = __float_as_uint(f);
    return (u & 0x80000000u) ? ~u : (u | 0x80000000u);
}
__device__ __forceinline__ float ord2f(unsigned u) {
    u = (u & 0x80000000u) ? (u & 0x7fffffffu) : ~u;
    return __uint_as_float(u);
}

__global__ void pool_init_kernel(unsigned* pool) {
    int i = blockIdx.x * blockDim.x + threadIdx.x;
    if (i < N_GRAPHS * 256) pool[i] = f2ord(-3.402823466e38f);
}

__global__ void pool_max_kernel(const float* __restrict__ h, const void* batch,
                                unsigned* __restrict__ pool)
{
    int i = blockIdx.x * blockDim.x + threadIdx.x;
    if (i >= N_NODES * 256) return;
    int n = i >> 8, f = i & 255;
    int g = load_idx(batch, n, g_b64);
    atomicMax(&pool[g * 256 + f], f2ord(h[i]));
}

__global__ void fc_kernel(const unsigned* __restrict__ pool,
                          const float* __restrict__ w, const float* __restrict__ b,
                          float* __restrict__ out)
{
    int t = threadIdx.x;
    if (t >= N_GRAPHS * 6) return;
    int g = t / 6, j = t % 6;
    float s = b[j];
    for (int k = 0; k < 256; k++)
        s += ord2f(pool[g * 256 + k]) * w[j * 256 + k];
    out[t] = s;
}

// ----------------------------- launch ---------------------------------------
static inline void run_gemm(const float* A, const float* B, const float* bias,
                            float* C, int N, int K, int M, int transB) {
    dim3 grid(M / BN, (N + BM - 1) / BM);
    gemm_kernel<<<grid, 256>>>(A, B, bias, C, N, K, M, transB);
}

extern "C" void kernel_launch(void* const* d_in, const int* in_sizes, int n_in,
                              void* d_out, int out_size)
{
    const float* x       = (const float*)d_in[0];
    const void*  edge    = d_in[1];
    const void*  batch   = d_in[2];
    const float* w1      = (const float*)d_in[3];
    const float* g1_wih  = (const float*)d_in[4];
    const float* g1_whh  = (const float*)d_in[5];
    const float* g1_bih  = (const float*)d_in[6];
    const float* g1_bhh  = (const float*)d_in[7];
    const float* w2      = (const float*)d_in[8];
    const float* g2_wih  = (const float*)d_in[9];
    const float* g2_whh  = (const float*)d_in[10];
    const float* g2_bih  = (const float*)d_in[11];
    const float* g2_bhh  = (const float*)d_in[12];
    const float* fc_w    = (const float*)d_in[13];
    const float* fc_b    = (const float*)d_in[14];

    float *h1, *h2, *m, *a, *gi, *gh;
    int *rowptr, *cnt, *cursor, *csr;
    unsigned* pool;
    cudaGetSymbolAddress((void**)&h1,     g_h1);
    cudaGetSymbolAddress((void**)&h2,     g_h2);
    cudaGetSymbolAddress((void**)&m,      g_m);
    cudaGetSymbolAddress((void**)&a,      g_a);
    cudaGetSymbolAddress((void**)&gi,     g_gi);
    cudaGetSymbolAddress((void**)&gh,     g_gh);
    cudaGetSymbolAddress((void**)&rowptr, g_rowptr);
    cudaGetSymbolAddress((void**)&cnt,    g_cnt);
    cudaGetSymbolAddress((void**)&cursor, g_cursor);
    cudaGetSymbolAddress((void**)&csr,    g_csr_src);
    cudaGetSymbolAddress((void**)&pool,   g_pool);

    // dtype detection (int32 vs int64 index arrays)
    detect_kernel<<<1, 1>>>(edge, batch);

    // CSR build (dst-sorted incoming-edge lists)
    zero_int_kernel<<<(N_NODES + 255) / 256, 256>>>(cnt, N_NODES);
    count_kernel<<<(N_EDGES + 255) / 256, 256>>>(edge, cnt);
    scan_kernel<<<1, 1024>>>(cnt, rowptr, N_NODES);
    copy_int_kernel<<<(N_NODES + 255) / 256, 256>>>(rowptr, cursor, N_NODES);
    fill_kernel<<<(N_EDGES + 255) / 256, 256>>>(edge, cursor, csr);

    // ---- stage 1: C = 128 ----
    for (int i = 0; i < 3; i++) {
        const float* h = (i == 0) ? x : h1;
        run_gemm(h, w1 + (long)i * 128 * 128, nullptr, m, N_NODES, 128, 128, 0);
        aggregate_kernel<<<N_NODES, 128>>>(m, a, rowptr, csr, 128);
        run_gemm(a, g1_wih, g1_bih, gi, N_NODES, 128, 384, 1);
        run_gemm(h, g1_whh, g1_bhh, gh, N_NODES, 128, 384, 1);
        gru_kernel<<<(N_NODES * 128 + 255) / 256, 256>>>(gi, gh, h, h1, 128);
    }

    // relu + pad 128 -> 256
    pad_relu_kernel<<<(N_NODES * 256 + 255) / 256, 256>>>(h1, h2);

    // ---- stage 2: C = 256 ----
    for (int i = 0; i < 3; i++) {
        run_gemm(h2, w2 + (long)i * 256 * 256, nullptr, m, N_NODES, 256, 256, 0);
        aggregate_kernel<<<N_NODES, 256>>>(m, a, rowptr, csr, 256);
        run_gemm(a, g2_wih, g2_bih, gi, N_NODES, 256, 768, 1);
        run_gemm(h2, g2_whh, g2_bhh, gh, N_NODES, 256, 768, 1);
        gru_kernel<<<(N_NODES * 256 + 255) / 256, 256>>>(gi, gh, h2, h2, 256);
    }

    // segment_max pool + FC
    pool_init_kernel<<<(N_GRAPHS * 256 + 255) / 256, 256>>>(pool);
    pool_max_kernel<<<(N_NODES * 256 + 255) / 256, 256>>>(h2, batch, pool);
    fc_kernel<<<1, N_GRAPHS * 6>>>(pool, fc_w, fc_b, (float*)d_out);
}

// round 3
// speedup vs baseline: 2.2811x; 2.2811x over previous
#include <cuda_runtime.h>
#include <cuda_bf16.h>
#include <math.h>
#include <stdint.h>

#define N_NODES 10000
#define N_EDGES 320000
#define N_GRAPHS 64

// ============================ device scratch =================================
__device__ __align__(16) float g_h1[N_NODES * 128];
__device__ __align__(16) float g_h2[N_NODES * 256];
__device__ __align__(16) float g_m [N_NODES * 256];
__device__ __align__(16) float g_gi[N_NODES * 768];
__device__ __align__(16) float g_gh[N_NODES * 768];
__device__ int   g_rowptr[N_NODES + 1];
__device__ int   g_cnt[N_NODES];
__device__ int   g_cursor[N_NODES];
__device__ int   g_csr_src[N_EDGES];
__device__ unsigned g_pool[N_GRAPHS * 256];
__device__ int   g_e64, g_b64;
// bf16 hi/lo buffers
__device__ __align__(16) __nv_bfloat16 g_hh[N_NODES * 256], g_hl[N_NODES * 256];
__device__ __align__(16) __nv_bfloat16 g_ah[N_NODES * 256], g_al[N_NODES * 256];
__device__ __align__(16) __nv_bfloat16 g_w1h[3*128*128], g_w1l[3*128*128];
__device__ __align__(16) __nv_bfloat16 g_w2h[3*256*256], g_w2l[3*256*256];
__device__ __align__(16) __nv_bfloat16 g_i1h[384*128],  g_i1l[384*128];
__device__ __align__(16) __nv_bfloat16 g_r1h[384*128],  g_r1l[384*128];
__device__ __align__(16) __nv_bfloat16 g_i2h[768*256],  g_i2l[768*256];
__device__ __align__(16) __nv_bfloat16 g_r2h[768*256],  g_r2l[768*256];

// ============================ dtype detection ================================
__global__ void detect_kernel(const void* edge, const void* batch) {
    __shared__ int eo, bo;
    int tid = threadIdx.x;
    if (tid == 0) { eo = 0; bo = 0; }
    __syncthreads();
    const unsigned* we = (const unsigned*)edge;
    const unsigned* wb = (const unsigned*)batch;
    for (int k = tid; k < 256; k += 128) {
        long i = (long)k * ((2L * N_EDGES) / 256);
        if (we[2 * i + 1] != 0u) atomicOr(&eo, 1);
        long j = (long)k * (N_NODES / 256);
        if (wb[2 * j + 1] != 0u) atomicOr(&bo, 1);
    }
    __syncthreads();
    if (tid == 0) { g_e64 = !eo; g_b64 = !bo; }
}
__device__ __forceinline__ int load_idx(const void* p, long i, int is64) {
    return is64 ? (int)((const long long*)p)[i] : ((const int*)p)[i];
}

// ============================ CSR build ======================================
__global__ void zero_int_kernel(int* p, int n) {
    int i = blockIdx.x * blockDim.x + threadIdx.x;
    if (i < n) p[i] = 0;
}
__global__ void count_kernel(const void* edge, int* cnt) {
    int e = blockIdx.x * blockDim.x + threadIdx.x;
    if (e >= N_EDGES) return;
    atomicAdd(&cnt[load_idx(edge, (long)N_EDGES + e, g_e64)], 1);
}
__global__ void scan_kernel(const int* __restrict__ cnt, int* __restrict__ rowptr, int n) {
    __shared__ int wsum[32];
    int tid = threadIdx.x, lane = tid & 31, wid = tid >> 5;
    int base = tid * 10;
    int v[10]; int s = 0;
    #pragma unroll
    for (int q = 0; q < 10; q++) {
        int i = base + q;
        int x = (i < n) ? cnt[i] : 0;
        s += x; v[q] = s;
    }
    int incl = s;
    #pragma unroll
    for (int o = 1; o < 32; o <<= 1) {
        int y = __shfl_up_sync(0xffffffffu, incl, o);
        if (lane >= o) incl += y;
    }
    if (lane == 31) wsum[wid] = incl;
    __syncthreads();
    if (wid == 0) {
        int t = wsum[lane];
        #pragma unroll
        for (int o = 1; o < 32; o <<= 1) {
            int y = __shfl_up_sync(0xffffffffu, t, o);
            if (lane >= o) t += y;
        }
        wsum[lane] = t;
    }
    __syncthreads();
    int excl = incl - s + (wid ? wsum[wid - 1] : 0);
    #pragma unroll
    for (int q = 0; q < 10; q++) {
        int i = base + q;
        if (i < n) rowptr[i + 1] = excl + v[q];
    }
    if (tid == 0) rowptr[0] = 0;
}
__global__ void copy_int_kernel(const int* src, int* dst, int n) {
    int i = blockIdx.x * blockDim.x + threadIdx.x;
    if (i < n) dst[i] = src[i];
}
__global__ void fill_kernel(const void* edge, int* cursor, int* csr_src) {
    int e = blockIdx.x * blockDim.x + threadIdx.x;
    if (e >= N_EDGES) return;
    int is64 = g_e64;
    int src = load_idx(edge, e, is64);
    int dst = load_idx(edge, (long)N_EDGES + e, is64);
    csr_src[atomicAdd(&cursor[dst], 1)] = src;
}

// ============================ hi/lo split ====================================
__device__ __forceinline__ void split1(float f, __nv_bfloat16& h, __nv_bfloat16& l) {
    h = __float2bfloat16(f);
    l = __float2bfloat16(f - __bfloat162float(h));
}
__global__ void split_kernel(const float* __restrict__ in, __nv_bfloat16* __restrict__ hi,
                             __nv_bfloat16* __restrict__ lo, int n4) {
    int i = blockIdx.x * blockDim.x + threadIdx.x;
    if (i >= n4) return;
    float4 v = ((const float4*)in)[i];
    __nv_bfloat16 h0, h1, h2, h3, l0, l1, l2, l3;
    split1(v.x, h0, l0); split1(v.y, h1, l1); split1(v.z, h2, l2); split1(v.w, h3, l3);
    ((__nv_bfloat162*)hi)[2*i]   = __halves2bfloat162(h0, h1);
    ((__nv_bfloat162*)hi)[2*i+1] = __halves2bfloat162(h2, h3);
    ((__nv_bfloat162*)lo)[2*i]   = __halves2bfloat162(l0, l1);
    ((__nv_bfloat162*)lo)[2*i+1] = __halves2bfloat162(l2, l3);
}
// w: [L,K,M] row-major  ->  out[l,m,k] = w[l,k,m]   (so x@w becomes A@B^T)
__global__ void tsplit_kernel(const float* __restrict__ w, __nv_bfloat16* __restrict__ hi,
                              __nv_bfloat16* __restrict__ lo, int K, int M, int L) {
    long idx = (long)blockIdx.x * blockDim.x + threadIdx.x;
    long total = (long)L * K * M;
    if (idx >= total) return;
    int per = K * M;
    int l = (int)(idx / per); int rem = (int)(idx % per);
    int m = rem / K, k = rem % K;
    __nv_bfloat16 h, lw;
    split1(w[(long)l * per + (long)k * M + m], h, lw);
    hi[idx] = h; lo[idx] = lw;
}

// ============================ HMMA GEMM ======================================
// C[Nrows,Ncols] = (Ahi+Alo)[Nrows,K] @ (Bhi+Blo)[Ncols,K]^T + bias
// 3 passes (hi*hi, lo*hi, hi*lo) accumulated in the same fp32 accumulators.
// Block 128x128, 8 warps (warp = 32x64), BK=32, reg-prefetch double buffer.
__device__ __forceinline__ void ldsm_x4(uint32_t* r, uint32_t addr) {
    asm volatile("ldmatrix.sync.aligned.m8n8.x4.shared.b16 {%0,%1,%2,%3}, [%4];"
        : "=r"(r[0]), "=r"(r[1]), "=r"(r[2]), "=r"(r[3]) : "r"(addr));
}
__device__ __forceinline__ void mma_16816(float* d, const uint32_t* a,
                                          uint32_t b0, uint32_t b1) {
    asm volatile("mma.sync.aligned.m16n8k16.row.col.f32.bf16.bf16.f32 "
        "{%0,%1,%2,%3}, {%4,%5,%6,%7}, {%8,%9}, {%0,%1,%2,%3};"
        : "+f"(d[0]), "+f"(d[1]), "+f"(d[2]), "+f"(d[3])
        : "r"(a[0]), "r"(a[1]), "r"(a[2]), "r"(a[3]), "r"(b0), "r"(b1));
}

__global__ __launch_bounds__(256) void mma_gemm_kernel(
    const __nv_bfloat16* __restrict__ Ahi, const __nv_bfloat16* __restrict__ Alo,
    const __nv_bfloat16* __restrict__ Bhi, const __nv_bfloat16* __restrict__ Blo,
    const float* __restrict__ bias, float* __restrict__ C,
    int Nrows, int K, int Ncols)
{
    __shared__ __nv_bfloat16 As[128][40];   // 32 + 8 pad -> conflict-free ldmatrix
    __shared__ __nv_bfloat16 Bs[128][40];
    int tid = threadIdx.x;
    int lane = tid & 31, wid = tid >> 5;
    int wm = (wid & 3) * 32;                // warp M offset
    int wn = (wid >> 2) * 64;               // warp N offset
    int row0 = blockIdx.y * 128, col0 = blockIdx.x * 128;

    float acc[2][8][4];
    #pragma unroll
    for (int i = 0; i < 2; i++)
        #pragma unroll
        for (int j = 0; j < 8; j++)
            #pragma unroll
            for (int q = 0; q < 4; q++) acc[i][j][q] = 0.f;

    int kc = K >> 5;        // 32-wide chunks per pass
    int nc = 3 * kc;

    uint4 pa[2], pb[2];
    // prefetch chunk 0
    {
        const __nv_bfloat16* sA = Ahi;
        const __nv_bfloat16* sB = Bhi;
        #pragma unroll
        for (int q = 0; q < 2; q++) {
            int idx = tid + q * 256;
            int r = idx >> 2, c8 = (idx & 3) << 3;
            int gr = row0 + r;
            uint4 va = make_uint4(0u,0u,0u,0u);
            if (gr < Nrows) va = *(const uint4*)(sA + (long)gr * K + c8);
            pa[q] = va;
            pb[q] = *(const uint4*)(sB + (long)(col0 + r) * K + c8);
        }
    }

    for (int c = 0; c < nc; c++) {
        #pragma unroll
        for (int q = 0; q < 2; q++) {
            int idx = tid + q * 256;
            int r = idx >> 2, c8 = (idx & 3) << 3;
            *(uint4*)&As[r][c8] = pa[q];
            *(uint4*)&Bs[r][c8] = pb[q];
        }
        __syncthreads();

        if (c + 1 < nc) {
            int cn = c + 1;
            int p = cn / kc, k0 = (cn % kc) << 5;
            const __nv_bfloat16* sA = (p == 1) ? Alo : Ahi;
            const __nv_bfloat16* sB = (p == 2) ? Blo : Bhi;
            #pragma unroll
            for (int q = 0; q < 2; q++) {
                int idx = tid + q * 256;
                int r = idx >> 2, c8 = (idx & 3) << 3;
                int gr = row0 + r;
                uint4 va = make_uint4(0u,0u,0u,0u);
                if (gr < Nrows) va = *(const uint4*)(sA + (long)gr * K + k0 + c8);
                pa[q] = va;
                pb[q] = *(const uint4*)(sB + (long)(col0 + r) * K + k0 + c8);
            }
        }

        #pragma unroll
        for (int ks = 0; ks < 2; ks++) {
            uint32_t af[2][4], bf[4][4];
            #pragma unroll
            for (int ti = 0; ti < 2; ti++) {
                int row = wm + ti * 16 + (lane & 15);
                int col = ks * 16 + (lane >> 4) * 8;
                uint32_t addr = (uint32_t)__cvta_generic_to_shared(&As[row][col]);
                ldsm_x4(af[ti], addr);
            }
            #pragma unroll
            for (int g = 0; g < 4; g++) {
                int row = wn + g * 16 + (lane & 7) + ((lane >> 4) << 3);
                int col = ks * 16 + ((lane >> 3) & 1) * 8;
                uint32_t addr = (uint32_t)__cvta_generic_to_shared(&Bs[row][col]);
                ldsm_x4(bf[g], addr);
            }
            #pragma unroll
            for (int ti = 0; ti < 2; ti++)
                #pragma unroll
                for (int g = 0; g < 4; g++) {
                    mma_16816(acc[ti][g*2],     af[ti], bf[g][0], bf[g][1]);
                    mma_16816(acc[ti][g*2 + 1], af[ti], bf[g][2], bf[g][3]);
                }
        }
        __syncthreads();
    }

    // epilogue: direct register -> global, bias fused
    #pragma unroll
    for (int ti = 0; ti < 2; ti++) {
        int rb = row0 + wm + ti * 16 + (lane >> 2);
        #pragma unroll
        for (int g = 0; g < 8; g++) {
            int col = col0 + wn + g * 8 + (lane & 3) * 2;
            float bx = 0.f, by = 0.f;
            if (bias) { bx = bias[col]; by = bias[col + 1]; }
            if (rb < Nrows)
                *(float2*)&C[(long)rb * Ncols + col] =
                    make_float2(acc[ti][g][0] + bx, acc[ti][g][1] + by);
            if (rb + 8 < Nrows)
                *(float2*)&C[(long)(rb + 8) * Ncols + col] =
                    make_float2(acc[ti][g][2] + bx, acc[ti][g][3] + by);
        }
    }
}

// ============================ aggregation (fused split) ======================
__global__ void aggregate_split_kernel(const float4* __restrict__ m4,
                                       __nv_bfloat16* __restrict__ ahi,
                                       __nv_bfloat16* __restrict__ alo,
                                       const int* __restrict__ rowptr,
                                       const int* __restrict__ csr, int C4)
{
    int n = blockIdx.x * 4 + threadIdx.y;
    if (n >= N_NODES) return;
    int f = threadIdx.x;
    int beg = rowptr[n], end = rowptr[n + 1];
    float4 acc = make_float4(0.f, 0.f, 0.f, 0.f);
    for (int j = beg; j < end; j++) {
        int s = csr[j];
        float4 v = m4[(long)s * C4 + f];
        acc.x += v.x; acc.y += v.y; acc.z += v.z; acc.w += v.w;
    }
    long o = ((long)n * C4 + f) * 2;
    __nv_bfloat16 h0,h1,h2,h3,l0,l1,l2,l3;
    split1(acc.x, h0, l0); split1(acc.y, h1, l1);
    split1(acc.z, h2, l2); split1(acc.w, h3, l3);
    ((__nv_bfloat162*)ahi)[o]   = __halves2bfloat162(h0, h1);
    ((__nv_bfloat162*)ahi)[o+1] = __halves2bfloat162(h2, h3);
    ((__nv_bfloat162*)alo)[o]   = __halves2bfloat162(l0, l1);
    ((__nv_bfloat162*)alo)[o+1] = __halves2bfloat162(l2, l3);
}

// ============================ GRU (fused split of new h) =====================
__global__ void gru_split_kernel(const float* __restrict__ gi, const float* __restrict__ gh,
                                 const float* __restrict__ h, float* __restrict__ hout,
                                 __nv_bfloat16* __restrict__ hhi, __nv_bfloat16* __restrict__ hlo,
                                 int C)
{
    int i = blockIdx.x * blockDim.x + threadIdx.x;
    if (i >= N_NODES * C) return;
    int n = i / C, f = i % C;
    const float* gir = gi + (long)n * 3 * C;
    const float* ghr = gh + (long)n * 3 * C;
    float ir = gir[f], iz = gir[C + f], in_ = gir[2 * C + f];
    float hr = ghr[f], hz = ghr[C + f], hn  = ghr[2 * C + f];
    float r = 1.f / (1.f + expf(-(ir + hr)));
    float z = 1.f / (1.f + expf(-(iz + hz)));
    float nn = tanhf(in_ + r * hn);
    float hv = (1.f - z) * nn + z * h[i];
    hout[i] = hv;
    __nv_bfloat16 bh, bl;
    split1(hv, bh, bl);
    hhi[i] = bh; hlo[i] = bl;
}

__global__ void pad_relu_split_kernel(const float* __restrict__ h1, float* __restrict__ h2,
                                      __nv_bfloat16* __restrict__ hhi, __nv_bfloat16* __restrict__ hlo)
{
    int i = blockIdx.x * blockDim.x + threadIdx.x;
    if (i >= N_NODES * 256) return;
    int n = i >> 8, f = i & 255;
    float v = (f < 128) ? fmaxf(h1[n * 128 + f], 0.f) : 0.f;
    h2[i] = v;
    __nv_bfloat16 bh, bl;
    split1(v, bh, bl);
    hhi[i] = bh; hlo[i] = bl;
}

// ============================ pooling + FC ===================================
__device__ __forceinline__ unsigned f2ord(float f) {
    unsigned u = __float_as_uint(f);
    return (u & 0x80000000u) ? ~u : (u | 0x80000000u);
}
__device__ __forceinline__ float ord2f(unsigned u) {
    u = (u & 0x80000000u) ? (u & 0x7fffffffu) : ~u;
    return __uint_as_float(u);
}
__global__ void pool_init_kernel(unsigned* pool) {
    int i = blockIdx.x * blockDim.x + threadIdx.x;
    if (i < N_GRAPHS * 256) pool[i] = f2ord(-3.402823466e38f);
}
__global__ void pool_max_kernel(const float* __restrict__ h, const void* batch,
                                unsigned* __restrict__ pool) {
    int i = blockIdx.x * blockDim.x + threadIdx.x;
    if (i >= N_NODES * 256) return;
    int n = i >> 8, f = i & 255;
    int g = load_idx(batch, n, g_b64);
    atomicMax(&pool[g * 256 + f], f2ord(h[i]));
}
__global__ void fc_kernel(const unsigned* __restrict__ pool, const float* __restrict__ w,
                          const float* __restrict__ b, float* __restrict__ out) {
    int t = threadIdx.x;
    if (t >= N_GRAPHS * 6) return;
    int g = t / 6, j = t % 6;
    float s = b[j];
    for (int k = 0; k < 256; k++)
        s += ord2f(pool[g * 256 + k]) * w[j * 256 + k];
    out[t] = s;
}

// ============================ launch =========================================
static inline void run_mma_gemm(const __nv_bfloat16* Ahi, const __nv_bfloat16* Alo,
                                const __nv_bfloat16* Bhi, const __nv_bfloat16* Blo,
                                const float* bias, float* C, int Nrows, int K, int Ncols) {
    dim3 grid(Ncols / 128, (Nrows + 127) / 128);
    mma_gemm_kernel<<<grid, 256>>>(Ahi, Alo, Bhi, Blo, bias, C, Nrows, K, Ncols);
}

extern "C" void kernel_launch(void* const* d_in, const int* in_sizes, int n_in,
                              void* d_out, int out_size)
{
    const float* x       = (const float*)d_in[0];
    const void*  edge    = d_in[1];
    const void*  batch   = d_in[2];
    const float* w1      = (const float*)d_in[3];
    const float* g1_wih  = (const float*)d_in[4];
    const float* g1_whh  = (const float*)d_in[5];
    const float* g1_bih  = (const float*)d_in[6];
    const float* g1_bhh  = (const float*)d_in[7];
    const float* w2      = (const float*)d_in[8];
    const float* g2_wih  = (const float*)d_in[9];
    const float* g2_whh  = (const float*)d_in[10];
    const float* g2_bih  = (const float*)d_in[11];
    const float* g2_bhh  = (const float*)d_in[12];
    const float* fc_w    = (const float*)d_in[13];
    const float* fc_b    = (const float*)d_in[14];

    float *h1, *h2, *m, *gi, *gh;
    int *rowptr, *cnt, *cursor, *csr;
    unsigned* pool;
    __nv_bfloat16 *hh, *hl, *ah, *al;
    __nv_bfloat16 *w1h, *w1l, *w2h, *w2l, *i1h, *i1l, *r1h, *r1l, *i2h, *i2l, *r2h, *r2l;
    cudaGetSymbolAddress((void**)&h1, g_h1);   cudaGetSymbolAddress((void**)&h2, g_h2);
    cudaGetSymbolAddress((void**)&m,  g_m);
    cudaGetSymbolAddress((void**)&gi, g_gi);   cudaGetSymbolAddress((void**)&gh, g_gh);
    cudaGetSymbolAddress((void**)&rowptr, g_rowptr); cudaGetSymbolAddress((void**)&cnt, g_cnt);
    cudaGetSymbolAddress((void**)&cursor, g_cursor); cudaGetSymbolAddress((void**)&csr, g_csr_src);
    cudaGetSymbolAddress((void**)&pool, g_pool);
    cudaGetSymbolAddress((void**)&hh, g_hh);   cudaGetSymbolAddress((void**)&hl, g_hl);
    cudaGetSymbolAddress((void**)&ah, g_ah);   cudaGetSymbolAddress((void**)&al, g_al);
    cudaGetSymbolAddress((void**)&w1h, g_w1h); cudaGetSymbolAddress((void**)&w1l, g_w1l);
    cudaGetSymbolAddress((void**)&w2h, g_w2h); cudaGetSymbolAddress((void**)&w2l, g_w2l);
    cudaGetSymbolAddress((void**)&i1h, g_i1h); cudaGetSymbolAddress((void**)&i1l, g_i1l);
    cudaGetSymbolAddress((void**)&r1h, g_r1h); cudaGetSymbolAddress((void**)&r1l, g_r1l);
    cudaGetSymbolAddress((void**)&i2h, g_i2h); cudaGetSymbolAddress((void**)&i2l, g_i2l);
    cudaGetSymbolAddress((void**)&r2h, g_r2h); cudaGetSymbolAddress((void**)&r2l, g_r2l);

    detect_kernel<<<1, 128>>>(edge, batch);

    // CSR build
    zero_int_kernel<<<(N_NODES + 255) / 256, 256>>>(cnt, N_NODES);
    count_kernel<<<(N_EDGES + 255) / 256, 256>>>(edge, cnt);
    scan_kernel<<<1, 1024>>>(cnt, rowptr, N_NODES);
    copy_int_kernel<<<(N_NODES + 255) / 256, 256>>>(rowptr, cursor, N_NODES);
    fill_kernel<<<(N_EDGES + 255) / 256, 256>>>(edge, cursor, csr);

    // weight conversions
    tsplit_kernel<<<(3*128*128 + 255) / 256, 256>>>(w1, w1h, w1l, 128, 128, 3);
    tsplit_kernel<<<(3*256*256 + 255) / 256, 256>>>(w2, w2h, w2l, 256, 256, 3);
    split_kernel<<<(384*128/4 + 255) / 256, 256>>>(g1_wih, i1h, i1l, 384*128/4);
    split_kernel<<<(384*128/4 + 255) / 256, 256>>>(g1_whh, r1h, r1l, 384*128/4);
    split_kernel<<<(768*256/4 + 255) / 256, 256>>>(g2_wih, i2h, i2l, 768*256/4);
    split_kernel<<<(768*256/4 + 255) / 256, 256>>>(g2_whh, r2h, r2l, 768*256/4);

    // ---- stage 1: C = 128 ----
    split_kernel<<<(N_NODES*128/4 + 255) / 256, 256>>>(x, hh, hl, N_NODES*128/4);
    for (int i = 0; i < 3; i++) {
        const float* h = (i == 0) ? x : h1;
        run_mma_gemm(hh, hl, w1h + (long)i*128*128, w1l + (long)i*128*128, nullptr, m,
                     N_NODES, 128, 128);
        aggregate_split_kernel<<<2500, dim3(32, 4)>>>((const float4*)m, ah, al, rowptr, csr, 32);
        run_mma_gemm(hh, hl, r1h, r1l, g1_bhh, gh, N_NODES, 128, 384);
        run_mma_gemm(ah, al, i1h, i1l, g1_bih, gi, N_NODES, 128, 384);
        gru_split_kernel<<<(N_NODES*128 + 255) / 256, 256>>>(gi, gh, h, h1, hh, hl, 128);
    }

    pad_relu_split_kernel<<<(N_NODES*256 + 255) / 256, 256>>>(h1, h2, hh, hl);

    // ---- stage 2: C = 256 ----
    for (int i = 0; i < 3; i++) {
        run_mma_gemm(hh, hl, w2h + (long)i*256*256, w2l + (long)i*256*256, nullptr, m,
                     N_NODES, 256, 256);
        aggregate_split_kernel<<<2500, dim3(64, 4)>>>((const float4*)m, ah, al, rowptr, csr, 64);
        run_mma_gemm(hh, hl, r2h, r2l, g2_bhh, gh, N_NODES, 256, 768);
        run_mma_gemm(ah, al, i2h, i2l, g2_bih, gi, N_NODES, 256, 768);
        gru_split_kernel<<<(N_NODES*256 + 255) / 256, 256>>>(gi, gh, h2, h2, hh, hl, 256);
    }

    // pooling + FC
    pool_init_kernel<<<(N_GRAPHS*256 + 255) / 256, 256>>>(pool);
    pool_max_kernel<<<(N_NODES*256 + 255) / 256, 256>>>(h2, batch, pool);
    fc_kernel<<<1, N_GRAPHS * 6>>>(pool, fc_w, fc_b, (float*)d_out);
}

// round 4
// speedup vs baseline: 2.5246x; 1.1067x over previous
#include <cuda_runtime.h>
#include <cuda_bf16.h>
#include <math.h>
#include <stdint.h>

#define N_NODES 10000
#define N_EDGES 320000
#define N_GRAPHS 64

// ============================ device scratch =================================
__device__ __align__(16) float g_h1[N_NODES * 128];
__device__ __align__(16) float g_h2[N_NODES * 256];
__device__ __align__(16) float g_m [N_NODES * 256];
__device__ __align__(16) float g_gi[N_NODES * 768];
__device__ __align__(16) float g_gh[N_NODES * 768];
__device__ int   g_rowptr[N_NODES + 1];
__device__ int   g_cnt[N_NODES];
__device__ int   g_cursor[N_NODES];
__device__ int   g_csr_src[N_EDGES];
__device__ unsigned g_pool[N_GRAPHS * 256];
__device__ int   g_e64, g_b64;
__device__ __align__(16) __nv_bfloat16 g_hh[N_NODES * 256], g_hl[N_NODES * 256];
__device__ __align__(16) __nv_bfloat16 g_ah[N_NODES * 256], g_al[N_NODES * 256];
__device__ __align__(16) __nv_bfloat16 g_w1h[3*128*128], g_w1l[3*128*128];
__device__ __align__(16) __nv_bfloat16 g_w2h[3*256*256], g_w2l[3*256*256];
__device__ __align__(16) __nv_bfloat16 g_i1h[384*128],  g_i1l[384*128];
__device__ __align__(16) __nv_bfloat16 g_r1h[384*128],  g_r1l[384*128];
__device__ __align__(16) __nv_bfloat16 g_i2h[768*256],  g_i2l[768*256];
__device__ __align__(16) __nv_bfloat16 g_r2h[768*256],  g_r2l[768*256];

// ============================ dtype detection ================================
__global__ void detect_kernel(const void* edge, const void* batch) {
    __shared__ int eo, bo;
    int tid = threadIdx.x;
    if (tid == 0) { eo = 0; bo = 0; }
    __syncthreads();
    const unsigned* we = (const unsigned*)edge;
    const unsigned* wb = (const unsigned*)batch;
    for (int k = tid; k < 256; k += 128) {
        long i = (long)k * ((2L * N_EDGES) / 256);
        if (we[2 * i + 1] != 0u) atomicOr(&eo, 1);
        long j = (long)k * (N_NODES / 256);
        if (wb[2 * j + 1] != 0u) atomicOr(&bo, 1);
    }
    __syncthreads();
    if (tid == 0) { g_e64 = !eo; g_b64 = !bo; }
}
__device__ __forceinline__ int load_idx(const void* p, long i, int is64) {
    return is64 ? (int)((const long long*)p)[i] : ((const int*)p)[i];
}

// ============================ CSR build ======================================
__global__ void zero_int_kernel(int* p, int n) {
    int i = blockIdx.x * blockDim.x + threadIdx.x;
    if (i < n) p[i] = 0;
}
__global__ void count_kernel(const void* edge, int* cnt) {
    int e = blockIdx.x * blockDim.x + threadIdx.x;
    if (e >= N_EDGES) return;
    atomicAdd(&cnt[load_idx(edge, (long)N_EDGES + e, g_e64)], 1);
}
__global__ void scan_kernel(const int* __restrict__ cnt, int* __restrict__ rowptr, int n) {
    __shared__ int wsum[32];
    int tid = threadIdx.x, lane = tid & 31, wid = tid >> 5;
    int base = tid * 10;
    int v[10]; int s = 0;
    #pragma unroll
    for (int q = 0; q < 10; q++) {
        int i = base + q;
        int x = (i < n) ? cnt[i] : 0;
        s += x; v[q] = s;
    }
    int incl = s;
    #pragma unroll
    for (int o = 1; o < 32; o <<= 1) {
        int y = __shfl_up_sync(0xffffffffu, incl, o);
        if (lane >= o) incl += y;
    }
    if (lane == 31) wsum[wid] = incl;
    __syncthreads();
    if (wid == 0) {
        int t = wsum[lane];
        #pragma unroll
        for (int o = 1; o < 32; o <<= 1) {
            int y = __shfl_up_sync(0xffffffffu, t, o);
            if (lane >= o) t += y;
        }
        wsum[lane] = t;
    }
    __syncthreads();
    int excl = incl - s + (wid ? wsum[wid - 1] : 0);
    #pragma unroll
    for (int q = 0; q < 10; q++) {
        int i = base + q;
        if (i < n) rowptr[i + 1] = excl + v[q];
    }
    if (tid == 0) rowptr[0] = 0;
}
__global__ void copy_int_kernel(const int* src, int* dst, int n) {
    int i = blockIdx.x * blockDim.x + threadIdx.x;
    if (i < n) dst[i] = src[i];
}
__global__ void fill_kernel(const void* edge, int* cursor, int* csr_src) {
    int e = blockIdx.x * blockDim.x + threadIdx.x;
    if (e >= N_EDGES) return;
    int is64 = g_e64;
    int src = load_idx(edge, e, is64);
    int dst = load_idx(edge, (long)N_EDGES + e, is64);
    csr_src[atomicAdd(&cursor[dst], 1)] = src;
}

// ============================ hi/lo split ====================================
__device__ __forceinline__ void split1(float f, __nv_bfloat16& h, __nv_bfloat16& l) {
    h = __float2bfloat16(f);
    l = __float2bfloat16(f - __bfloat162float(h));
}
__global__ void split_kernel(const float* __restrict__ in, __nv_bfloat16* __restrict__ hi,
                             __nv_bfloat16* __restrict__ lo, int n4) {
    int i = blockIdx.x * blockDim.x + threadIdx.x;
    if (i >= n4) return;
    float4 v = ((const float4*)in)[i];
    __nv_bfloat16 h0, h1, h2, h3, l0, l1, l2, l3;
    split1(v.x, h0, l0); split1(v.y, h1, l1); split1(v.z, h2, l2); split1(v.w, h3, l3);
    ((__nv_bfloat162*)hi)[2*i]   = __halves2bfloat162(h0, h1);
    ((__nv_bfloat162*)hi)[2*i+1] = __halves2bfloat162(h2, h3);
    ((__nv_bfloat162*)lo)[2*i]   = __halves2bfloat162(l0, l1);
    ((__nv_bfloat162*)lo)[2*i+1] = __halves2bfloat162(l2, l3);
}
// w: [L,K,M] row-major  ->  out[l,m,k] = w[l,k,m]
__global__ void tsplit_kernel(const float* __restrict__ w, __nv_bfloat16* __restrict__ hi,
                              __nv_bfloat16* __restrict__ lo, int K, int M, int L) {
    long idx = (long)blockIdx.x * blockDim.x + threadIdx.x;
    long total = (long)L * K * M;
    if (idx >= total) return;
    int per = K * M;
    int l = (int)(idx / per); int rem = (int)(idx % per);
    int m = rem / K, k = rem % K;
    __nv_bfloat16 h, lw;
    split1(w[(long)l * per + (long)k * M + m], h, lw);
    hi[idx] = h; lo[idx] = lw;
}

// ============================ HMMA GEMM (cp.async 3-stage) ===================
// C[Nrows,Ncols] = (Ahi+Alo)[Nrows,K] @ (Bhi+Blo)[Ncols,K]^T + bias
// 3 passes (hi*hi, lo*hi, hi*lo). Block 128x128, 4 warps (warp = 64x64),
// BK=64, 3-stage cp.async pipeline, single __syncthreads per chunk.
#define LDA   72
#define TILEE (128 * LDA)
#define GEMM_SMEM (6 * TILEE * 2)

__device__ __forceinline__ void ldsm_x4(uint32_t* r, uint32_t addr) {
    asm volatile("ldmatrix.sync.aligned.m8n8.x4.shared.b16 {%0,%1,%2,%3}, [%4];"
        : "=r"(r[0]), "=r"(r[1]), "=r"(r[2]), "=r"(r[3]) : "r"(addr));
}
__device__ __forceinline__ void mma_16816(float* d, const uint32_t* a,
                                          uint32_t b0, uint32_t b1) {
    asm volatile("mma.sync.aligned.m16n8k16.row.col.f32.bf16.bf16.f32 "
        "{%0,%1,%2,%3}, {%4,%5,%6,%7}, {%8,%9}, {%0,%1,%2,%3};"
        : "+f"(d[0]), "+f"(d[1]), "+f"(d[2]), "+f"(d[3])
        : "r"(a[0]), "r"(a[1]), "r"(a[2]), "r"(a[3]), "r"(b0), "r"(b1));
}
__device__ __forceinline__ void cp16(uint32_t dst, const void* src, bool pred) {
    int sz = pred ? 16 : 0;
    asm volatile("cp.async.cg.shared.global [%0], [%1], 16, %2;"
        :: "r"(dst), "l"(src), "r"(sz) : "memory");
}
__device__ __forceinline__ void gemm_issue(
    int c, int nc, int kc, int tid, int row0, int col0, int Nrows, int K,
    uint32_t smu,
    const __nv_bfloat16* __restrict__ Ahi, const __nv_bfloat16* __restrict__ Alo,
    const __nv_bfloat16* __restrict__ Bhi, const __nv_bfloat16* __restrict__ Blo)
{
    if (c < nc) {
        int s = c % 3;
        int p = c / kc, k0 = (c % kc) << 6;
        const __nv_bfloat16* sA = (p == 1) ? Alo : Ahi;
        const __nv_bfloat16* sB = (p == 2) ? Blo : Bhi;
        uint32_t baseA = smu + (uint32_t)(s * TILEE) * 2;
        uint32_t baseB = smu + (uint32_t)((3 + s) * TILEE) * 2;
        #pragma unroll
        for (int q = 0; q < 8; q++) {
            int idx = q * 128 + tid;
            int row = idx >> 3, seg = (idx & 7) << 3;
            int gr = row0 + row;
            long grc = (gr < Nrows) ? gr : 0;
            cp16(baseA + (uint32_t)(row * LDA + seg) * 2,
                 sA + grc * K + k0 + seg, gr < Nrows);
            cp16(baseB + (uint32_t)(row * LDA + seg) * 2,
                 sB + (long)(col0 + row) * K + k0 + seg, true);
        }
    }
    asm volatile("cp.async.commit_group;" ::: "memory");
}

__global__ __launch_bounds__(128, 2) void mma_gemm_kernel(
    const __nv_bfloat16* __restrict__ Ahi, const __nv_bfloat16* __restrict__ Alo,
    const __nv_bfloat16* __restrict__ Bhi, const __nv_bfloat16* __restrict__ Blo,
    const float* __restrict__ bias, float* __restrict__ C,
    int Nrows, int K, int Ncols)
{
    extern __shared__ __nv_bfloat16 smg[];
    uint32_t smu = (uint32_t)__cvta_generic_to_shared(smg);
    int tid = threadIdx.x, lane = tid & 31, wid = tid >> 5;
    int wm = (wid & 1) * 64, wn = (wid >> 1) * 64;
    int row0 = blockIdx.y * 128, col0 = blockIdx.x * 128;

    float acc[4][8][4];
    #pragma unroll
    for (int i = 0; i < 4; i++)
        #pragma unroll
        for (int j = 0; j < 8; j++)
            #pragma unroll
            for (int q = 0; q < 4; q++) acc[i][j][q] = 0.f;

    int kc = K >> 6, nc = 3 * kc;

    gemm_issue(0, nc, kc, tid, row0, col0, Nrows, K, smu, Ahi, Alo, Bhi, Blo);
    gemm_issue(1, nc, kc, tid, row0, col0, Nrows, K, smu, Ahi, Alo, Bhi, Blo);

    for (int c = 0; c < nc; c++) {
        asm volatile("cp.async.wait_group 1;" ::: "memory");
        __syncthreads();
        gemm_issue(c + 2, nc, kc, tid, row0, col0, Nrows, K, smu, Ahi, Alo, Bhi, Blo);

        int s = c % 3;
        uint32_t baseA = smu + (uint32_t)(s * TILEE) * 2;
        uint32_t baseB = smu + (uint32_t)((3 + s) * TILEE) * 2;
        #pragma unroll
        for (int ks = 0; ks < 4; ks++) {
            uint32_t af[4][4], bf[4][4];
            #pragma unroll
            for (int ti = 0; ti < 4; ti++) {
                int row = wm + ti * 16 + (lane & 15);
                int col = ks * 16 + (lane >> 4) * 8;
                ldsm_x4(af[ti], baseA + (uint32_t)(row * LDA + col) * 2);
            }
            #pragma unroll
            for (int g = 0; g < 4; g++) {
                int row = wn + g * 16 + (lane & 7) + ((lane >> 4) << 3);
                int col = ks * 16 + ((lane >> 3) & 1) * 8;
                ldsm_x4(bf[g], baseB + (uint32_t)(row * LDA + col) * 2);
            }
            #pragma unroll
            for (int ti = 0; ti < 4; ti++)
                #pragma unroll
                for (int g = 0; g < 4; g++) {
                    mma_16816(acc[ti][g*2],     af[ti], bf[g][0], bf[g][1]);
                    mma_16816(acc[ti][g*2 + 1], af[ti], bf[g][2], bf[g][3]);
                }
        }
    }

    // epilogue: registers -> global, bias fused
    #pragma unroll
    for (int ti = 0; ti < 4; ti++) {
        int rb = row0 + wm + ti * 16 + (lane >> 2);
        #pragma unroll
        for (int g = 0; g < 8; g++) {
            int col = col0 + wn + g * 8 + (lane & 3) * 2;
            float bx = 0.f, by = 0.f;
            if (bias) { bx = bias[col]; by = bias[col + 1]; }
            if (rb < Nrows)
                *(float2*)&C[(long)rb * Ncols + col] =
                    make_float2(acc[ti][g][0] + bx, acc[ti][g][1] + by);
            if (rb + 8 < Nrows)
                *(float2*)&C[(long)(rb + 8) * Ncols + col] =
                    make_float2(acc[ti][g][2] + bx, acc[ti][g][3] + by);
        }
    }
}

// ============================ aggregation (fused split) ======================
__global__ void aggregate_split_kernel(const float4* __restrict__ m4,
                                       __nv_bfloat16* __restrict__ ahi,
                                       __nv_bfloat16* __restrict__ alo,
                                       const int* __restrict__ rowptr,
                                       const int* __restrict__ csr, int C4)
{
    int n = blockIdx.x * 4 + threadIdx.y;
    if (n >= N_NODES) return;
    int f = threadIdx.x;
    int beg = rowptr[n], end = rowptr[n + 1];
    float4 acc = make_float4(0.f, 0.f, 0.f, 0.f);
    for (int j = beg; j < end; j++) {
        int s = csr[j];
        float4 v = m4[(long)s * C4 + f];
        acc.x += v.x; acc.y += v.y; acc.z += v.z; acc.w += v.w;
    }
    long o = ((long)n * C4 + f) * 2;
    __nv_bfloat16 h0,h1,h2,h3,l0,l1,l2,l3;
    split1(acc.x, h0, l0); split1(acc.y, h1, l1);
    split1(acc.z, h2, l2); split1(acc.w, h3, l3);
    ((__nv_bfloat162*)ahi)[o]   = __halves2bfloat162(h0, h1);
    ((__nv_bfloat162*)ahi)[o+1] = __halves2bfloat162(h2, h3);
    ((__nv_bfloat162*)alo)[o]   = __halves2bfloat162(l0, l1);
    ((__nv_bfloat162*)alo)[o+1] = __halves2bfloat162(l2, l3);
}

// ============================ GRU (fused split of new h) =====================
__global__ void gru_split_kernel(const float* __restrict__ gi, const float* __restrict__ gh,
                                 const float* __restrict__ h, float* __restrict__ hout,
                                 __nv_bfloat16* __restrict__ hhi, __nv_bfloat16* __restrict__ hlo,
                                 int C)
{
    int i = blockIdx.x * blockDim.x + threadIdx.x;
    if (i >= N_NODES * C) return;
    int n = i / C, f = i % C;
    const float* gir = gi + (long)n * 3 * C;
    const float* ghr = gh + (long)n * 3 * C;
    float ir = gir[f], iz = gir[C + f], in_ = gir[2 * C + f];
    float hr = ghr[f], hz = ghr[C + f], hn  = ghr[2 * C + f];
    float r = 1.f / (1.f + expf(-(ir + hr)));
    float z = 1.f / (1.f + expf(-(iz + hz)));
    float nn = tanhf(in_ + r * hn);
    float hv = (1.f - z) * nn + z * h[i];
    hout[i] = hv;
    __nv_bfloat16 bh, bl;
    split1(hv, bh, bl);
    hhi[i] = bh; hlo[i] = bl;
}

__global__ void pad_relu_split_kernel(const float* __restrict__ h1, float* __restrict__ h2,
                                      __nv_bfloat16* __restrict__ hhi, __nv_bfloat16* __restrict__ hlo)
{
    int i = blockIdx.x * blockDim.x + threadIdx.x;
    if (i >= N_NODES * 256) return;
    int n = i >> 8, f = i & 255;
    float v = (f < 128) ? fmaxf(h1[n * 128 + f], 0.f) : 0.f;
    h2[i] = v;
    __nv_bfloat16 bh, bl;
    split1(v, bh, bl);
    hhi[i] = bh; hlo[i] = bl;
}

// ============================ pooling + FC ===================================
__device__ __forceinline__ unsigned f2ord(float f) {
    unsigned u = __float_as_uint(f);
    return (u & 0x80000000u) ? ~u : (u | 0x80000000u);
}
__device__ __forceinline__ float ord2f(unsigned u) {
    u = (u & 0x80000000u) ? (u & 0x7fffffffu) : ~u;
    return __uint_as_float(u);
}
__global__ void pool_init_kernel(unsigned* pool) {
    int i = blockIdx.x * blockDim.x + threadIdx.x;
    if (i < N_GRAPHS * 256) pool[i] = f2ord(-3.402823466e38f);
}
__global__ void pool_max_kernel(const float* __restrict__ h, const void* batch,
                                unsigned* __restrict__ pool) {
    int i = blockIdx.x * blockDim.x + threadIdx.x;
    if (i >= N_NODES * 256) return;
    int n = i >> 8, f = i & 255;
    int g = load_idx(batch, n, g_b64);
    atomicMax(&pool[g * 256 + f], f2ord(h[i]));
}
__global__ void fc_kernel(const unsigned* __restrict__ pool, const float* __restrict__ w,
                          const float* __restrict__ b, float* __restrict__ out) {
    int t = threadIdx.x;
    if (t >= N_GRAPHS * 6) return;
    int g = t / 6, j = t % 6;
    float s = b[j];
    for (int k = 0; k < 256; k++)
        s += ord2f(pool[g * 256 + k]) * w[j * 256 + k];
    out[t] = s;
}

// ============================ launch =========================================
static inline void run_mma_gemm(const __nv_bfloat16* Ahi, const __nv_bfloat16* Alo,
                                const __nv_bfloat16* Bhi, const __nv_bfloat16* Blo,
                                const float* bias, float* C, int Nrows, int K, int Ncols) {
    dim3 grid(Ncols / 128, (Nrows + 127) / 128);
    mma_gemm_kernel<<<grid, 128, GEMM_SMEM>>>(Ahi, Alo, Bhi, Blo, bias, C, Nrows, K, Ncols);
}

extern "C" void kernel_launch(void* const* d_in, const int* in_sizes, int n_in,
                              void* d_out, int out_size)
{
    const float* x       = (const float*)d_in[0];
    const void*  edge    = d_in[1];
    const void*  batch   = d_in[2];
    const float* w1      = (const float*)d_in[3];
    const float* g1_wih  = (const float*)d_in[4];
    const float* g1_whh  = (const float*)d_in[5];
    const float* g1_bih  = (const float*)d_in[6];
    const float* g1_bhh  = (const float*)d_in[7];
    const float* w2      = (const float*)d_in[8];
    const float* g2_wih  = (const float*)d_in[9];
    const float* g2_whh  = (const float*)d_in[10];
    const float* g2_bih  = (const float*)d_in[11];
    const float* g2_bhh  = (const float*)d_in[12];
    const float* fc_w    = (const float*)d_in[13];
    const float* fc_b    = (const float*)d_in[14];

    cudaFuncSetAttribute(mma_gemm_kernel, cudaFuncAttributeMaxDynamicSharedMemorySize,
                         GEMM_SMEM);

    float *h1, *h2, *m, *gi, *gh;
    int *rowptr, *cnt, *cursor, *csr;
    unsigned* pool;
    __nv_bfloat16 *hh, *hl, *ah, *al;
    __nv_bfloat16 *w1h, *w1l, *w2h, *w2l, *i1h, *i1l, *r1h, *r1l, *i2h, *i2l, *r2h, *r2l;
    cudaGetSymbolAddress((void**)&h1, g_h1);   cudaGetSymbolAddress((void**)&h2, g_h2);
    cudaGetSymbolAddress((void**)&m,  g_m);
    cudaGetSymbolAddress((void**)&gi, g_gi);   cudaGetSymbolAddress((void**)&gh, g_gh);
    cudaGetSymbolAddress((void**)&rowptr, g_rowptr); cudaGetSymbolAddress((void**)&cnt, g_cnt);
    cudaGetSymbolAddress((void**)&cursor, g_cursor); cudaGetSymbolAddress((void**)&csr, g_csr_src);
    cudaGetSymbolAddress((void**)&pool, g_pool);
    cudaGetSymbolAddress((void**)&hh, g_hh);   cudaGetSymbolAddress((void**)&hl, g_hl);
    cudaGetSymbolAddress((void**)&ah, g_ah);   cudaGetSymbolAddress((void**)&al, g_al);
    cudaGetSymbolAddress((void**)&w1h, g_w1h); cudaGetSymbolAddress((void**)&w1l, g_w1l);
    cudaGetSymbolAddress((void**)&w2h, g_w2h); cudaGetSymbolAddress((void**)&w2l, g_w2l);
    cudaGetSymbolAddress((void**)&i1h, g_i1h); cudaGetSymbolAddress((void**)&i1l, g_i1l);
    cudaGetSymbolAddress((void**)&r1h, g_r1h); cudaGetSymbolAddress((void**)&r1l, g_r1l);
    cudaGetSymbolAddress((void**)&i2h, g_i2h); cudaGetSymbolAddress((void**)&i2l, g_i2l);
    cudaGetSymbolAddress((void**)&r2h, g_r2h); cudaGetSymbolAddress((void**)&r2l, g_r2l);

    detect_kernel<<<1, 128>>>(edge, batch);

    // CSR build
    zero_int_kernel<<<(N_NODES + 255) / 256, 256>>>(cnt, N_NODES);
    count_kernel<<<(N_EDGES + 255) / 256, 256>>>(edge, cnt);
    scan_kernel<<<1, 1024>>>(cnt, rowptr, N_NODES);
    copy_int_kernel<<<(N_NODES + 255) / 256, 256>>>(rowptr, cursor, N_NODES);
    fill_kernel<<<(N_EDGES + 255) / 256, 256>>>(edge, cursor, csr);

    // weight conversions
    tsplit_kernel<<<(3*128*128 + 255) / 256, 256>>>(w1, w1h, w1l, 128, 128, 3);
    tsplit_kernel<<<(3*256*256 + 255) / 256, 256>>>(w2, w2h, w2l, 256, 256, 3);
    split_kernel<<<(384*128/4 + 255) / 256, 256>>>(g1_wih, i1h, i1l, 384*128/4);
    split_kernel<<<(384*128/4 + 255) / 256, 256>>>(g1_whh, r1h, r1l, 384*128/4);
    split_kernel<<<(768*256/4 + 255) / 256, 256>>>(g2_wih, i2h, i2l, 768*256/4);
    split_kernel<<<(768*256/4 + 255) / 256, 256>>>(g2_whh, r2h, r2l, 768*256/4);

    // ---- stage 1: C = 128 ----
    split_kernel<<<(N_NODES*128/4 + 255) / 256, 256>>>(x, hh, hl, N_NODES*128/4);
    for (int i = 0; i < 3; i++) {
        const float* h = (i == 0) ? x : h1;
        run_mma_gemm(hh, hl, w1h + (long)i*128*128, w1l + (long)i*128*128, nullptr, m,
                     N_NODES, 128, 128);
        aggregate_split_kernel<<<2500, dim3(32, 4)>>>((const float4*)m, ah, al, rowptr, csr, 32);
        run_mma_gemm(hh, hl, r1h, r1l, g1_bhh, gh, N_NODES, 128, 384);
        run_mma_gemm(ah, al, i1h, i1l, g1_bih, gi, N_NODES, 128, 384);
        gru_split_kernel<<<(N_NODES*128 + 255) / 256, 256>>>(gi, gh, h, h1, hh, hl, 128);
    }

    pad_relu_split_kernel<<<(N_NODES*256 + 255) / 256, 256>>>(h1, h2, hh, hl);

    // ---- stage 2: C = 256 ----
    for (int i = 0; i < 3; i++) {
        run_mma_gemm(hh, hl, w2h + (long)i*256*256, w2l + (long)i*256*256, nullptr, m,
                     N_NODES, 256, 256);
        aggregate_split_kernel<<<2500, dim3(64, 4)>>>((const float4*)m, ah, al, rowptr, csr, 64);
        run_mma_gemm(hh, hl, r2h, r2l, g2_bhh, gh, N_NODES, 256, 768);
        run_mma_gemm(ah, al, i2h, i2l, g2_bih, gi, N_NODES, 256, 768);
        gru_split_kernel<<<(N_NODES*256 + 255) / 256, 256>>>(gi, gh, h2, h2, hh, hl, 256);
    }

    // pooling + FC
    pool_init_kernel<<<(N_GRAPHS*256 + 255) / 256, 256>>>(pool);
    pool_max_kernel<<<(N_NODES*256 + 255) / 256, 256>>>(h2, batch, pool);
    fc_kernel<<<1, N_GRAPHS * 6>>>(pool, fc_w, fc_b, (float*)d_out);
}

// round 5
// speedup vs baseline: 2.6533x; 1.0510x over previous
#include <cuda_runtime.h>
#include <cuda_bf16.h>
#include <math.h>
#include <stdint.h>

#define N_NODES 10000
#define N_EDGES 320000
#define N_GRAPHS 64

// ============================ device scratch =================================
__device__ __align__(16) float g_h1[N_NODES * 128];
__device__ __align__(16) float g_h2[N_NODES * 256];
__device__ __align__(16) float g_gi[N_NODES * 768];
__device__ __align__(16) float g_gh[N_NODES * 768];
__device__ int   g_rowptr[N_NODES + 1];
__device__ int   g_cnt[N_NODES];
__device__ int   g_cursor[N_NODES];
__device__ int   g_csr_src[N_EDGES];
__device__ unsigned g_pool[N_GRAPHS * 256];
__device__ int   g_e64, g_b64;
__device__ __align__(16) __nv_bfloat16 g_hh[N_NODES * 256], g_hl[N_NODES * 256];
__device__ __align__(16) __nv_bfloat16 g_ah[N_NODES * 256], g_al[N_NODES * 256];
// untransposed weight splits (for V precompute)
__device__ __align__(16) __nv_bfloat16 g_w1uh[3*128*128], g_w1ul[3*128*128];
__device__ __align__(16) __nv_bfloat16 g_w2uh[3*256*256], g_w2ul[3*256*256];
// GRU weight splits
__device__ __align__(16) __nv_bfloat16 g_i1h[384*128],  g_i1l[384*128];
__device__ __align__(16) __nv_bfloat16 g_r1h[384*128],  g_r1l[384*128];
__device__ __align__(16) __nv_bfloat16 g_i2h[768*256],  g_i2l[768*256];
__device__ __align__(16) __nv_bfloat16 g_r2h[768*256],  g_r2l[768*256];
// folded weights V_i = Wih @ W_i^T  (bf16 hi/lo)
__device__ __align__(16) __nv_bfloat16 g_v1h[3*384*128], g_v1l[3*384*128];
__device__ __align__(16) __nv_bfloat16 g_v2h[3*768*256], g_v2l[3*768*256];

// ============================ dtype detection ================================
__global__ void detect_kernel(const void* edge, const void* batch) {
    __shared__ int eo, bo;
    int tid = threadIdx.x;
    if (tid == 0) { eo = 0; bo = 0; }
    __syncthreads();
    const unsigned* we = (const unsigned*)edge;
    const unsigned* wb = (const unsigned*)batch;
    for (int k = tid; k < 256; k += 128) {
        long i = (long)k * ((2L * N_EDGES) / 256);
        if (we[2 * i + 1] != 0u) atomicOr(&eo, 1);
        long j = (long)k * (N_NODES / 256);
        if (wb[2 * j + 1] != 0u) atomicOr(&bo, 1);
    }
    __syncthreads();
    if (tid == 0) { g_e64 = !eo; g_b64 = !bo; }
}
__device__ __forceinline__ int load_idx(const void* p, long i, int is64) {
    return is64 ? (int)((const long long*)p)[i] : ((const int*)p)[i];
}

// ============================ CSR build ======================================
__global__ void zero_int_kernel(int* p, int n) {
    int i = blockIdx.x * blockDim.x + threadIdx.x;
    if (i < n) p[i] = 0;
}
__global__ void count_kernel(const void* edge, int* cnt) {
    int e = blockIdx.x * blockDim.x + threadIdx.x;
    if (e >= N_EDGES) return;
    atomicAdd(&cnt[load_idx(edge, (long)N_EDGES + e, g_e64)], 1);
}
__global__ void scan_kernel(const int* __restrict__ cnt, int* __restrict__ rowptr, int n) {
    __shared__ int wsum[32];
    int tid = threadIdx.x, lane = tid & 31, wid = tid >> 5;
    int base = tid * 10;
    int v[10]; int s = 0;
    #pragma unroll
    for (int q = 0; q < 10; q++) {
        int i = base + q;
        int x = (i < n) ? cnt[i] : 0;
        s += x; v[q] = s;
    }
    int incl = s;
    #pragma unroll
    for (int o = 1; o < 32; o <<= 1) {
        int y = __shfl_up_sync(0xffffffffu, incl, o);
        if (lane >= o) incl += y;
    }
    if (lane == 31) wsum[wid] = incl;
    __syncthreads();
    if (wid == 0) {
        int t = wsum[lane];
        #pragma unroll
        for (int o = 1; o < 32; o <<= 1) {
            int y = __shfl_up_sync(0xffffffffu, t, o);
            if (lane >= o) t += y;
        }
        wsum[lane] = t;
    }
    __syncthreads();
    int excl = incl - s + (wid ? wsum[wid - 1] : 0);
    #pragma unroll
    for (int q = 0; q < 10; q++) {
        int i = base + q;
        if (i < n) rowptr[i + 1] = excl + v[q];
    }
    if (tid == 0) rowptr[0] = 0;
}
__global__ void copy_int_kernel(const int* src, int* dst, int n) {
    int i = blockIdx.x * blockDim.x + threadIdx.x;
    if (i < n) dst[i] = src[i];
}
__global__ void fill_kernel(const void* edge, int* cursor, int* csr_src) {
    int e = blockIdx.x * blockDim.x + threadIdx.x;
    if (e >= N_EDGES) return;
    int is64 = g_e64;
    int src = load_idx(edge, e, is64);
    int dst = load_idx(edge, (long)N_EDGES + e, is64);
    csr_src[atomicAdd(&cursor[dst], 1)] = src;
}

// ============================ hi/lo split ====================================
__device__ __forceinline__ void split1(float f, __nv_bfloat16& h, __nv_bfloat16& l) {
    h = __float2bfloat16(f);
    l = __float2bfloat16(f - __bfloat162float(h));
}
__global__ void split_kernel(const float* __restrict__ in, __nv_bfloat16* __restrict__ hi,
                             __nv_bfloat16* __restrict__ lo, int n4) {
    int i = blockIdx.x * blockDim.x + threadIdx.x;
    if (i >= n4) return;
    float4 v = ((const float4*)in)[i];
    __nv_bfloat16 h0, h1, h2, h3, l0, l1, l2, l3;
    split1(v.x, h0, l0); split1(v.y, h1, l1); split1(v.z, h2, l2); split1(v.w, h3, l3);
    ((__nv_bfloat162*)hi)[2*i]   = __halves2bfloat162(h0, h1);
    ((__nv_bfloat162*)hi)[2*i+1] = __halves2bfloat162(h2, h3);
    ((__nv_bfloat162*)lo)[2*i]   = __halves2bfloat162(l0, l1);
    ((__nv_bfloat162*)lo)[2*i+1] = __halves2bfloat162(l2, l3);
}

// ============================ HMMA GEMM (64x128 tile, dual-op) ===============
// C[Nrows,Ncols] = (Ah+Al)[Nrows,K] @ (Bh+Bl)[Ncols,K]^T + bias
// 3 passes (hi*hi, lo*hi, hi*lo). Block 64x128, 4 warps (warp=32x64), BK=64,
// 3-stage cp.async pipeline. blockIdx.z selects op set (fused dual GEMM).
// If Chi != null, writes bf16 hi/lo split instead of fp32.
struct GOp {
    const __nv_bfloat16 *Ah, *Al, *Bh, *Bl;
    const float* bias;
    float* C;
    __nv_bfloat16 *Chi, *Clo;
};
#define ATILE (64 * 72)
#define BTILE (128 * 72)
#define GEMM_SMEM (3 * (ATILE + BTILE) * 2)

__device__ __forceinline__ void ldsm_x4(uint32_t* r, uint32_t addr) {
    asm volatile("ldmatrix.sync.aligned.m8n8.x4.shared.b16 {%0,%1,%2,%3}, [%4];"
        : "=r"(r[0]), "=r"(r[1]), "=r"(r[2]), "=r"(r[3]) : "r"(addr));
}
__device__ __forceinline__ void mma_16816(float* d, const uint32_t* a,
                                          uint32_t b0, uint32_t b1) {
    asm volatile("mma.sync.aligned.m16n8k16.row.col.f32.bf16.bf16.f32 "
        "{%0,%1,%2,%3}, {%4,%5,%6,%7}, {%8,%9}, {%0,%1,%2,%3};"
        : "+f"(d[0]), "+f"(d[1]), "+f"(d[2]), "+f"(d[3])
        : "r"(a[0]), "r"(a[1]), "r"(a[2]), "r"(a[3]), "r"(b0), "r"(b1));
}
__device__ __forceinline__ void cp16(uint32_t dst, const void* src, bool pred) {
    int sz = pred ? 16 : 0;
    asm volatile("cp.async.cg.shared.global [%0], [%1], 16, %2;"
        :: "r"(dst), "l"(src), "r"(sz) : "memory");
}
__device__ __forceinline__ void gemm_issue(
    const GOp& o, int c, int nc, int kc, int tid, int row0, int col0,
    int Nrows, int K, uint32_t smu)
{
    if (c < nc) {
        int s = c % 3;
        int p = c / kc, k0 = (c % kc) << 6;
        const __nv_bfloat16* sA = (p == 1) ? o.Al : o.Ah;
        const __nv_bfloat16* sB = (p == 2) ? o.Bl : o.Bh;
        uint32_t bA = smu + (uint32_t)(s * ATILE) * 2;
        uint32_t bB = smu + (uint32_t)(3 * ATILE + s * BTILE) * 2;
        #pragma unroll
        for (int q = 0; q < 4; q++) {
            int idx = q * 128 + tid;             // 0..511
            int row = idx >> 3, seg = (idx & 7) << 3;
            int gr = row0 + row;
            long grc = (gr < Nrows) ? gr : 0;
            cp16(bA + (uint32_t)(row * 72 + seg) * 2, sA + grc * K + k0 + seg, gr < Nrows);
        }
        #pragma unroll
        for (int q = 0; q < 8; q++) {
            int idx = q * 128 + tid;             // 0..1023
            int row = idx >> 3, seg = (idx & 7) << 3;
            cp16(bB + (uint32_t)(row * 72 + seg) * 2,
                 sB + (long)(col0 + row) * K + k0 + seg, true);
        }
    }
    asm volatile("cp.async.commit_group;" ::: "memory");
}

__global__ __launch_bounds__(128, 2) void gemm64_kernel(
    GOp o0, GOp o1, int Nrows, int K, int Ncols)
{
    GOp o = (blockIdx.z == 0) ? o0 : o1;
    extern __shared__ __nv_bfloat16 smg[];
    uint32_t smu = (uint32_t)__cvta_generic_to_shared(smg);
    int tid = threadIdx.x, lane = tid & 31, wid = tid >> 5;
    int wm = (wid & 1) * 32, wn = (wid >> 1) * 64;
    int row0 = blockIdx.y * 64, col0 = blockIdx.x * 128;

    float acc[2][8][4];
    #pragma unroll
    for (int i = 0; i < 2; i++)
        #pragma unroll
        for (int j = 0; j < 8; j++)
            #pragma unroll
            for (int q = 0; q < 4; q++) acc[i][j][q] = 0.f;

    int kc = K >> 6, nc = 3 * kc;
    gemm_issue(o, 0, nc, kc, tid, row0, col0, Nrows, K, smu);
    gemm_issue(o, 1, nc, kc, tid, row0, col0, Nrows, K, smu);

    for (int c = 0; c < nc; c++) {
        asm volatile("cp.async.wait_group 1;" ::: "memory");
        __syncthreads();
        gemm_issue(o, c + 2, nc, kc, tid, row0, col0, Nrows, K, smu);

        int s = c % 3;
        uint32_t bA = smu + (uint32_t)(s * ATILE) * 2;
        uint32_t bB = smu + (uint32_t)(3 * ATILE + s * BTILE) * 2;
        #pragma unroll
        for (int ks = 0; ks < 4; ks++) {
            uint32_t af[2][4], bf[4][4];
            #pragma unroll
            for (int ti = 0; ti < 2; ti++) {
                int row = wm + ti * 16 + (lane & 15);
                int col = ks * 16 + (lane >> 4) * 8;
                ldsm_x4(af[ti], bA + (uint32_t)(row * 72 + col) * 2);
            }
            #pragma unroll
            for (int g = 0; g < 4; g++) {
                int row = wn + g * 16 + (lane & 7) + ((lane >> 4) << 3);
                int col = ks * 16 + ((lane >> 3) & 1) * 8;
                ldsm_x4(bf[g], bB + (uint32_t)(row * 72 + col) * 2);
            }
            #pragma unroll
            for (int ti = 0; ti < 2; ti++)
                #pragma unroll
                for (int g = 0; g < 4; g++) {
                    mma_16816(acc[ti][g*2],     af[ti], bf[g][0], bf[g][1]);
                    mma_16816(acc[ti][g*2 + 1], af[ti], bf[g][2], bf[g][3]);
                }
        }
    }

    // epilogue
    #pragma unroll
    for (int ti = 0; ti < 2; ti++) {
        int rb = row0 + wm + ti * 16 + (lane >> 2);
        #pragma unroll
        for (int g = 0; g < 8; g++) {
            int col = col0 + wn + g * 8 + (lane & 3) * 2;
            float bx = 0.f, by = 0.f;
            if (o.bias) { bx = o.bias[col]; by = o.bias[col + 1]; }
            float v0 = acc[ti][g][0] + bx, v1 = acc[ti][g][1] + by;
            float v2 = acc[ti][g][2] + bx, v3 = acc[ti][g][3] + by;
            if (o.Chi) {
                __nv_bfloat16 h0,h1,l0,l1;
                if (rb < Nrows) {
                    split1(v0, h0, l0); split1(v1, h1, l1);
                    *(__nv_bfloat162*)&o.Chi[(long)rb * Ncols + col] = __halves2bfloat162(h0, h1);
                    *(__nv_bfloat162*)&o.Clo[(long)rb * Ncols + col] = __halves2bfloat162(l0, l1);
                }
                if (rb + 8 < Nrows) {
                    split1(v2, h0, l0); split1(v3, h1, l1);
                    *(__nv_bfloat162*)&o.Chi[(long)(rb+8) * Ncols + col] = __halves2bfloat162(h0, h1);
                    *(__nv_bfloat162*)&o.Clo[(long)(rb+8) * Ncols + col] = __halves2bfloat162(l0, l1);
                }
            } else {
                if (rb < Nrows)
                    *(float2*)&o.C[(long)rb * Ncols + col] = make_float2(v0, v1);
                if (rb + 8 < Nrows)
                    *(float2*)&o.C[(long)(rb + 8) * Ncols + col] = make_float2(v2, v3);
            }
        }
    }
}

// ============================ aggregation (fused split) ======================
// a[n,:] = sum over incoming edges of h[src,:]; emits bf16 hi/lo directly.
__global__ void aggregate_split_kernel(const float4* __restrict__ h4,
                                       __nv_bfloat16* __restrict__ ahi,
                                       __nv_bfloat16* __restrict__ alo,
                                       const int* __restrict__ rowptr,
                                       const int* __restrict__ csr, int C4)
{
    int n = blockIdx.x * 4 + threadIdx.y;
    if (n >= N_NODES) return;
    int f = threadIdx.x;
    int beg = rowptr[n], end = rowptr[n + 1];
    float4 acc = make_float4(0.f, 0.f, 0.f, 0.f);
    for (int j = beg; j < end; j++) {
        int s = csr[j];
        float4 v = h4[(long)s * C4 + f];
        acc.x += v.x; acc.y += v.y; acc.z += v.z; acc.w += v.w;
    }
    long o = ((long)n * C4 + f) * 2;
    __nv_bfloat16 h0,h1,h2,h3,l0,l1,l2,l3;
    split1(acc.x, h0, l0); split1(acc.y, h1, l1);
    split1(acc.z, h2, l2); split1(acc.w, h3, l3);
    ((__nv_bfloat162*)ahi)[o]   = __halves2bfloat162(h0, h1);
    ((__nv_bfloat162*)ahi)[o+1] = __halves2bfloat162(h2, h3);
    ((__nv_bfloat162*)alo)[o]   = __halves2bfloat162(l0, l1);
    ((__nv_bfloat162*)alo)[o+1] = __halves2bfloat162(l2, l3);
}

// ============================ GRU (fused split of new h) =====================
__global__ void gru_split_kernel(const float* __restrict__ gi, const float* __restrict__ gh,
                                 const float* __restrict__ h, float* __restrict__ hout,
                                 __nv_bfloat16* __restrict__ hhi, __nv_bfloat16* __restrict__ hlo,
                                 int C)
{
    int i = blockIdx.x * blockDim.x + threadIdx.x;
    if (i >= N_NODES * C) return;
    int n = i / C, f = i % C;
    const float* gir = gi + (long)n * 3 * C;
    const float* ghr = gh + (long)n * 3 * C;
    float ir = gir[f], iz = gir[C + f], in_ = gir[2 * C + f];
    float hr = ghr[f], hz = ghr[C + f], hn  = ghr[2 * C + f];
    float r = 1.f / (1.f + expf(-(ir + hr)));
    float z = 1.f / (1.f + expf(-(iz + hz)));
    float nn = tanhf(in_ + r * hn);
    float hv = (1.f - z) * nn + z * h[i];
    hout[i] = hv;
    __nv_bfloat16 bh, bl;
    split1(hv, bh, bl);
    hhi[i] = bh; hlo[i] = bl;
}

__global__ void pad_relu_split_kernel(const float* __restrict__ h1, float* __restrict__ h2,
                                      __nv_bfloat16* __restrict__ hhi, __nv_bfloat16* __restrict__ hlo)
{
    int i = blockIdx.x * blockDim.x + threadIdx.x;
    if (i >= N_NODES * 256) return;
    int n = i >> 8, f = i & 255;
    float v = (f < 128) ? fmaxf(h1[n * 128 + f], 0.f) : 0.f;
    h2[i] = v;
    __nv_bfloat16 bh, bl;
    split1(v, bh, bl);
    hhi[i] = bh; hlo[i] = bl;
}

// ============================ pooling + FC ===================================
__device__ __forceinline__ unsigned f2ord(float f) {
    unsigned u = __float_as_uint(f);
    return (u & 0x80000000u) ? ~u : (u | 0x80000000u);
}
__device__ __forceinline__ float ord2f(unsigned u) {
    u = (u & 0x80000000u) ? (u & 0x7fffffffu) : ~u;
    return __uint_as_float(u);
}
__global__ void pool_init_kernel(unsigned* pool) {
    int i = blockIdx.x * blockDim.x + threadIdx.x;
    if (i < N_GRAPHS * 256) pool[i] = f2ord(-3.402823466e38f);
}
__global__ void pool_max_kernel(const float* __restrict__ h, const void* batch,
                                unsigned* __restrict__ pool) {
    int i = blockIdx.x * blockDim.x + threadIdx.x;
    if (i >= N_NODES * 256) return;
    int n = i >> 8, f = i & 255;
    int g = load_idx(batch, n, g_b64);
    atomicMax(&pool[g * 256 + f], f2ord(h[i]));
}
__global__ void fc_kernel(const unsigned* __restrict__ pool, const float* __restrict__ w,
                          const float* __restrict__ b, float* __restrict__ out) {
    int t = threadIdx.x;
    if (t >= N_GRAPHS * 6) return;
    int g = t / 6, j = t % 6;
    float s = b[j];
    for (int k = 0; k < 256; k++)
        s += ord2f(pool[g * 256 + k]) * w[j * 256 + k];
    out[t] = s;
}

// ============================ launch =========================================
static inline GOp mkop(const __nv_bfloat16* Ah, const __nv_bfloat16* Al,
                       const __nv_bfloat16* Bh, const __nv_bfloat16* Bl,
                       const float* bias, float* C,
                       __nv_bfloat16* Chi = nullptr, __nv_bfloat16* Clo = nullptr) {
    GOp o; o.Ah = Ah; o.Al = Al; o.Bh = Bh; o.Bl = Bl;
    o.bias = bias; o.C = C; o.Chi = Chi; o.Clo = Clo; return o;
}

extern "C" void kernel_launch(void* const* d_in, const int* in_sizes, int n_in,
                              void* d_out, int out_size)
{
    const float* x       = (const float*)d_in[0];
    const void*  edge    = d_in[1];
    const void*  batch   = d_in[2];
    const float* w1      = (const float*)d_in[3];
    const float* g1_wih  = (const float*)d_in[4];
    const float* g1_whh  = (const float*)d_in[5];
    const float* g1_bih  = (const float*)d_in[6];
    const float* g1_bhh  = (const float*)d_in[7];
    const float* w2      = (const float*)d_in[8];
    const float* g2_wih  = (const float*)d_in[9];
    const float* g2_whh  = (const float*)d_in[10];
    const float* g2_bih  = (const float*)d_in[11];
    const float* g2_bhh  = (const float*)d_in[12];
    const float* fc_w    = (const float*)d_in[13];
    const float* fc_b    = (const float*)d_in[14];

    cudaFuncSetAttribute(gemm64_kernel, cudaFuncAttributeMaxDynamicSharedMemorySize,
                         GEMM_SMEM);

    float *h1, *h2, *gi, *gh;
    int *rowptr, *cnt, *cursor, *csr;
    unsigned* pool;
    __nv_bfloat16 *hh, *hl, *ah, *al;
    __nv_bfloat16 *w1uh, *w1ul, *w2uh, *w2ul;
    __nv_bfloat16 *i1h, *i1l, *r1h, *r1l, *i2h, *i2l, *r2h, *r2l;
    __nv_bfloat16 *v1h, *v1l, *v2h, *v2l;
    cudaGetSymbolAddress((void**)&h1, g_h1);   cudaGetSymbolAddress((void**)&h2, g_h2);
    cudaGetSymbolAddress((void**)&gi, g_gi);   cudaGetSymbolAddress((void**)&gh, g_gh);
    cudaGetSymbolAddress((void**)&rowptr, g_rowptr); cudaGetSymbolAddress((void**)&cnt, g_cnt);
    cudaGetSymbolAddress((void**)&cursor, g_cursor); cudaGetSymbolAddress((void**)&csr, g_csr_src);
    cudaGetSymbolAddress((void**)&pool, g_pool);
    cudaGetSymbolAddress((void**)&hh, g_hh);   cudaGetSymbolAddress((void**)&hl, g_hl);
    cudaGetSymbolAddress((void**)&ah, g_ah);   cudaGetSymbolAddress((void**)&al, g_al);
    cudaGetSymbolAddress((void**)&w1uh, g_w1uh); cudaGetSymbolAddress((void**)&w1ul, g_w1ul);
    cudaGetSymbolAddress((void**)&w2uh, g_w2uh); cudaGetSymbolAddress((void**)&w2ul, g_w2ul);
    cudaGetSymbolAddress((void**)&i1h, g_i1h); cudaGetSymbolAddress((void**)&i1l, g_i1l);
    cudaGetSymbolAddress((void**)&r1h, g_r1h); cudaGetSymbolAddress((void**)&r1l, g_r1l);
    cudaGetSymbolAddress((void**)&i2h, g_i2h); cudaGetSymbolAddress((void**)&i2l, g_i2l);
    cudaGetSymbolAddress((void**)&r2h, g_r2h); cudaGetSymbolAddress((void**)&r2l, g_r2l);
    cudaGetSymbolAddress((void**)&v1h, g_v1h); cudaGetSymbolAddress((void**)&v1l, g_v1l);
    cudaGetSymbolAddress((void**)&v2h, g_v2h); cudaGetSymbolAddress((void**)&v2l, g_v2l);

    detect_kernel<<<1, 128>>>(edge, batch);

    // CSR build
    zero_int_kernel<<<(N_NODES + 255) / 256, 256>>>(cnt, N_NODES);
    count_kernel<<<(N_EDGES + 255) / 256, 256>>>(edge, cnt);
    scan_kernel<<<1, 1024>>>(cnt, rowptr, N_NODES);
    copy_int_kernel<<<(N_NODES + 255) / 256, 256>>>(rowptr, cursor, N_NODES);
    fill_kernel<<<(N_EDGES + 255) / 256, 256>>>(edge, cursor, csr);

    // weight splits (all untransposed, row-major as stored)
    split_kernel<<<(3*128*128/4 + 255) / 256, 256>>>(w1, w1uh, w1ul, 3*128*128/4);
    split_kernel<<<(3*256*256/4 + 255) / 256, 256>>>(w2, w2uh, w2ul, 3*256*256/4);
    split_kernel<<<(384*128/4 + 255) / 256, 256>>>(g1_wih, i1h, i1l, 384*128/4);
    split_kernel<<<(384*128/4 + 255) / 256, 256>>>(g1_whh, r1h, r1l, 384*128/4);
    split_kernel<<<(768*256/4 + 255) / 256, 256>>>(g2_wih, i2h, i2l, 768*256/4);
    split_kernel<<<(768*256/4 + 255) / 256, 256>>>(g2_whh, r2h, r2l, 768*256/4);
    split_kernel<<<(N_NODES*128/4 + 255) / 256, 256>>>(x, hh, hl, N_NODES*128/4);

    // V precompute: V_i[c,j] = sum_k wih[c,k] * w_i[j,k]  -> [3C, C] bf16 hi/lo
    for (int i = 0; i < 3; i++) {
        GOp o = mkop(i1h, i1l, w1uh + (long)i*128*128, w1ul + (long)i*128*128,
                     nullptr, nullptr, v1h + (long)i*384*128, v1l + (long)i*384*128);
        gemm64_kernel<<<dim3(1, 6, 1), 128, GEMM_SMEM>>>(o, o, 384, 128, 128);
    }
    for (int i = 0; i < 3; i++) {
        GOp o = mkop(i2h, i2l, w2uh + (long)i*256*256, w2ul + (long)i*256*256,
                     nullptr, nullptr, v2h + (long)i*768*256, v2l + (long)i*768*256);
        gemm64_kernel<<<dim3(2, 12, 1), 128, GEMM_SMEM>>>(o, o, 768, 256, 256);
    }

    // ---- stage 1: C = 128 ----
    for (int i = 0; i < 3; i++) {
        const float* h = (i == 0) ? x : h1;
        aggregate_split_kernel<<<2500, dim3(32, 4)>>>((const float4*)h, ah, al, rowptr, csr, 32);
        GOp ogi = mkop(ah, al, v1h + (long)i*384*128, v1l + (long)i*384*128, g1_bih, gi);
        GOp ogh = mkop(hh, hl, r1h, r1l, g1_bhh, gh);
        gemm64_kernel<<<dim3(3, 157, 2), 128, GEMM_SMEM>>>(ogi, ogh, N_NODES, 128, 384);
        gru_split_kernel<<<(N_NODES*128 + 255) / 256, 256>>>(gi, gh, h, h1, hh, hl, 128);
    }

    pad_relu_split_kernel<<<(N_NODES*256 + 255) / 256, 256>>>(h1, h2, hh, hl);

    // ---- stage 2: C = 256 ----
    for (int i = 0; i < 3; i++) {
        aggregate_split_kernel<<<2500, dim3(64, 4)>>>((const float4*)h2, ah, al, rowptr, csr, 64);
        GOp ogi = mkop(ah, al, v2h + (long)i*768*256, v2l + (long)i*768*256, g2_bih, gi);
        GOp ogh = mkop(hh, hl, r2h, r2l, g2_bhh, gh);
        gemm64_kernel<<<dim3(6, 157, 2), 128, GEMM_SMEM>>>(ogi, ogh, N_NODES, 256, 768);
        gru_split_kernel<<<(N_NODES*256 + 255) / 256, 256>>>(gi, gh, h2, h2, hh, hl, 256);
    }

    // pooling + FC
    pool_init_kernel<<<(N_GRAPHS*256 + 255) / 256, 256>>>(pool);
    pool_max_kernel<<<(N_NODES*256 + 255) / 256, 256>>>(h2, batch, pool);
    fc_kernel<<<1, N_GRAPHS * 6>>>(pool, fc_w, fc_b, (float*)d_out);
}

// round 6
// speedup vs baseline: 3.1596x; 1.1908x over previous
#include <cuda_runtime.h>
#include <cuda_bf16.h>
#include <math.h>
#include <stdint.h>

#define N_NODES 10000
#define N_EDGES 320000
#define N_GRAPHS 64

// ============================ device scratch =================================
__device__ __align__(16) float g_h1[N_NODES * 128];
__device__ __align__(16) float g_h2[N_NODES * 256];
__device__ __align__(16) float g_gi[N_NODES * 768];
__device__ __align__(16) float g_gh[N_NODES * 768];
__device__ int   g_rowptr[N_NODES + 1];
__device__ int   g_cnt[N_NODES];
__device__ int   g_cursor[N_NODES];
__device__ int   g_csr_src[N_EDGES];
__device__ unsigned g_pool[N_GRAPHS * 256];
__device__ int   g_e64, g_b64;
__device__ __align__(16) __nv_bfloat16 g_hh[N_NODES * 256], g_hl[N_NODES * 256];
__device__ __align__(16) __nv_bfloat16 g_ah[N_NODES * 256], g_al[N_NODES * 256];
__device__ __align__(16) __nv_bfloat16 g_w1uh[3*128*128], g_w1ul[3*128*128];
__device__ __align__(16) __nv_bfloat16 g_w2uh[3*256*256], g_w2ul[3*256*256];
__device__ __align__(16) __nv_bfloat16 g_i1h[384*128],  g_i1l[384*128];
__device__ __align__(16) __nv_bfloat16 g_r1h[384*128],  g_r1l[384*128];
__device__ __align__(16) __nv_bfloat16 g_i2h[768*256],  g_i2l[768*256];
__device__ __align__(16) __nv_bfloat16 g_r2h[768*256],  g_r2l[768*256];
__device__ __align__(16) __nv_bfloat16 g_v1h[3*384*128], g_v1l[3*384*128];
__device__ __align__(16) __nv_bfloat16 g_v2h[3*768*256], g_v2l[3*768*256];

// ============================ helpers ========================================
__device__ __forceinline__ unsigned f2ord(float f) {
    unsigned u = __float_as_uint(f);
    return (u & 0x80000000u) ? ~u : (u | 0x80000000u);
}
__device__ __forceinline__ float ord2f(unsigned u) {
    u = (u & 0x80000000u) ? (u & 0x7fffffffu) : ~u;
    return __uint_as_float(u);
}
__device__ __forceinline__ int load_idx(const void* p, long i, int is64) {
    return is64 ? (int)((const long long*)p)[i] : ((const int*)p)[i];
}
__device__ __forceinline__ void split1(float f, __nv_bfloat16& h, __nv_bfloat16& l) {
    h = __float2bfloat16(f);
    l = __float2bfloat16(f - __bfloat162float(h));
}

// ============================ prep: zero cnt + pool init + detect ============
__global__ void prep_kernel(const void* edge, const void* batch,
                            int* cnt, unsigned* pool) {
    int b = blockIdx.x, tid = threadIdx.x;
    int i = b * 256 + tid;
    if (i < N_NODES) cnt[i] = 0;
    if (i < N_GRAPHS * 256) pool[i] = f2ord(-3.402823466e38f);
    if (b == 64) {
        __shared__ int eo, bo;
        if (tid == 0) { eo = 0; bo = 0; }
        __syncthreads();
        const unsigned* we = (const unsigned*)edge;
        const unsigned* wb = (const unsigned*)batch;
        long ie = (long)tid * ((2L * N_EDGES) / 256);
        if (we[2 * ie + 1] != 0u) atomicOr(&eo, 1);
        long jb = (long)tid * (N_NODES / 256);
        if (wb[2 * jb + 1] != 0u) atomicOr(&bo, 1);
        __syncthreads();
        if (tid == 0) { g_e64 = !eo; g_b64 = !bo; }
    }
}

// ============================ CSR build ======================================
__global__ void count_kernel(const void* edge, int* cnt) {
    int e = blockIdx.x * blockDim.x + threadIdx.x;
    if (e >= N_EDGES) return;
    atomicAdd(&cnt[load_idx(edge, (long)N_EDGES + e, g_e64)], 1);
}
// single block scan; also emits cursor (= exclusive prefix = rowptr[i])
__global__ void scan_kernel(const int* __restrict__ cnt, int* __restrict__ rowptr,
                            int* __restrict__ cursor, int n) {
    __shared__ int wsum[32];
    int tid = threadIdx.x, lane = tid & 31, wid = tid >> 5;
    int base = tid * 10;
    int v[10]; int s = 0;
    #pragma unroll
    for (int q = 0; q < 10; q++) {
        int i = base + q;
        int x = (i < n) ? cnt[i] : 0;
        s += x; v[q] = s;
    }
    int incl = s;
    #pragma unroll
    for (int o = 1; o < 32; o <<= 1) {
        int y = __shfl_up_sync(0xffffffffu, incl, o);
        if (lane >= o) incl += y;
    }
    if (lane == 31) wsum[wid] = incl;
    __syncthreads();
    if (wid == 0) {
        int t = wsum[lane];
        #pragma unroll
        for (int o = 1; o < 32; o <<= 1) {
            int y = __shfl_up_sync(0xffffffffu, t, o);
            if (lane >= o) t += y;
        }
        wsum[lane] = t;
    }
    __syncthreads();
    int excl = incl - s + (wid ? wsum[wid - 1] : 0);
    #pragma unroll
    for (int q = 0; q < 10; q++) {
        int i = base + q;
        if (i < n) {
            rowptr[i + 1] = excl + v[q];
            cursor[i] = excl + (q ? v[q - 1] : 0);
        }
    }
    if (tid == 0) rowptr[0] = 0;
}
__global__ void fill_kernel(const void* edge, int* cursor, int* csr_src) {
    int e = blockIdx.x * blockDim.x + threadIdx.x;
    if (e >= N_EDGES) return;
    int is64 = g_e64;
    int src = load_idx(edge, e, is64);
    int dst = load_idx(edge, (long)N_EDGES + e, is64);
    csr_src[atomicAdd(&cursor[dst], 1)] = src;
}

// ============================ merged hi/lo split =============================
struct SJob { const float* in; __nv_bfloat16* hi; __nv_bfloat16* lo; int n4; };
struct SJobs { SJob j[7]; };
__global__ void split_all_kernel(SJobs js) {
    SJob jb = js.j[blockIdx.z];
    int i = blockIdx.x * 256 + threadIdx.x;
    if (i >= jb.n4) return;
    float4 v = ((const float4*)jb.in)[i];
    __nv_bfloat16 h0, h1, h2, h3, l0, l1, l2, l3;
    split1(v.x, h0, l0); split1(v.y, h1, l1); split1(v.z, h2, l2); split1(v.w, h3, l3);
    ((__nv_bfloat162*)jb.hi)[2*i]   = __halves2bfloat162(h0, h1);
    ((__nv_bfloat162*)jb.hi)[2*i+1] = __halves2bfloat162(h2, h3);
    ((__nv_bfloat162*)jb.lo)[2*i]   = __halves2bfloat162(l0, l1);
    ((__nv_bfloat162*)jb.lo)[2*i+1] = __halves2bfloat162(l2, l3);
}

// ============================ HMMA GEMM (128x128, 8 warps, triple-op) ========
struct GOp {
    const __nv_bfloat16 *Ah, *Al, *Bh, *Bl;
    const float* bias;
    float* C;
    __nv_bfloat16 *Chi, *Clo;
};
struct GTriple { GOp o[3]; };
#define TILE128 (128 * 72)
#define GEMM_SMEM (3 * 2 * TILE128 * 2)

__device__ __forceinline__ void ldsm_x4(uint32_t* r, uint32_t addr) {
    asm volatile("ldmatrix.sync.aligned.m8n8.x4.shared.b16 {%0,%1,%2,%3}, [%4];"
        : "=r"(r[0]), "=r"(r[1]), "=r"(r[2]), "=r"(r[3]) : "r"(addr));
}
__device__ __forceinline__ void mma_16816(float* d, const uint32_t* a,
                                          uint32_t b0, uint32_t b1) {
    asm volatile("mma.sync.aligned.m16n8k16.row.col.f32.bf16.bf16.f32 "
        "{%0,%1,%2,%3}, {%4,%5,%6,%7}, {%8,%9}, {%0,%1,%2,%3};"
        : "+f"(d[0]), "+f"(d[1]), "+f"(d[2]), "+f"(d[3])
        : "r"(a[0]), "r"(a[1]), "r"(a[2]), "r"(a[3]), "r"(b0), "r"(b1));
}
__device__ __forceinline__ void cp16(uint32_t dst, const void* src, bool pred) {
    int sz = pred ? 16 : 0;
    asm volatile("cp.async.cg.shared.global [%0], [%1], 16, %2;"
        :: "r"(dst), "l"(src), "r"(sz) : "memory");
}
__device__ __forceinline__ void gemm_issue(
    const GOp& o, int c, int nc, int kc, int tid, int row0, int col0,
    int Nrows, int K, uint32_t smu)
{
    if (c < nc) {
        int s = c % 3;
        int p = c / kc, k0 = (c % kc) << 6;
        const __nv_bfloat16* sA = (p == 1) ? o.Al : o.Ah;
        const __nv_bfloat16* sB = (p == 2) ? o.Bl : o.Bh;
        uint32_t bA = smu + (uint32_t)(s * TILE128) * 2;
        uint32_t bB = smu + (uint32_t)((3 + s) * TILE128) * 2;
        #pragma unroll
        for (int q = 0; q < 4; q++) {
            int idx = q * 256 + tid;             // 0..1023
            int row = idx >> 3, seg = (idx & 7) << 3;
            int gr = row0 + row;
            long grc = (gr < Nrows) ? gr : 0;
            cp16(bA + (uint32_t)(row * 72 + seg) * 2, sA + grc * K + k0 + seg, gr < Nrows);
            cp16(bB + (uint32_t)(row * 72 + seg) * 2,
                 sB + (long)(col0 + row) * K + k0 + seg, true);
        }
    }
    asm volatile("cp.async.commit_group;" ::: "memory");
}

__global__ __launch_bounds__(256, 2) void gemm256_kernel(
    GTriple t, int Nrows, int K, int Ncols)
{
    GOp o = t.o[blockIdx.z];
    extern __shared__ __nv_bfloat16 smg[];
    uint32_t smu = (uint32_t)__cvta_generic_to_shared(smg);
    int tid = threadIdx.x, lane = tid & 31, wid = tid >> 5;
    int wm = (wid & 3) * 32, wn = (wid >> 2) * 64;
    int row0 = blockIdx.y * 128, col0 = blockIdx.x * 128;

    float acc[2][8][4];
    #pragma unroll
    for (int i = 0; i < 2; i++)
        #pragma unroll
        for (int j = 0; j < 8; j++)
            #pragma unroll
            for (int q = 0; q < 4; q++) acc[i][j][q] = 0.f;

    int kc = K >> 6, nc = 3 * kc;
    gemm_issue(o, 0, nc, kc, tid, row0, col0, Nrows, K, smu);
    gemm_issue(o, 1, nc, kc, tid, row0, col0, Nrows, K, smu);

    for (int c = 0; c < nc; c++) {
        asm volatile("cp.async.wait_group 1;" ::: "memory");
        __syncthreads();
        gemm_issue(o, c + 2, nc, kc, tid, row0, col0, Nrows, K, smu);

        int s = c % 3;
        uint32_t bA = smu + (uint32_t)(s * TILE128) * 2;
        uint32_t bB = smu + (uint32_t)((3 + s) * TILE128) * 2;
        #pragma unroll
        for (int ks = 0; ks < 4; ks++) {
            uint32_t af[2][4], bf[4][4];
            #pragma unroll
            for (int ti = 0; ti < 2; ti++) {
                int row = wm + ti * 16 + (lane & 15);
                int col = ks * 16 + (lane >> 4) * 8;
                ldsm_x4(af[ti], bA + (uint32_t)(row * 72 + col) * 2);
            }
            #pragma unroll
            for (int g = 0; g < 4; g++) {
                int row = wn + g * 16 + (lane & 7) + ((lane >> 4) << 3);
                int col = ks * 16 + ((lane >> 3) & 1) * 8;
                ldsm_x4(bf[g], bB + (uint32_t)(row * 72 + col) * 2);
            }
            #pragma unroll
            for (int ti = 0; ti < 2; ti++)
                #pragma unroll
                for (int g = 0; g < 4; g++) {
                    mma_16816(acc[ti][g*2],     af[ti], bf[g][0], bf[g][1]);
                    mma_16816(acc[ti][g*2 + 1], af[ti], bf[g][2], bf[g][3]);
                }
        }
    }

    // epilogue
    #pragma unroll
    for (int ti = 0; ti < 2; ti++) {
        int rb = row0 + wm + ti * 16 + (lane >> 2);
        #pragma unroll
        for (int g = 0; g < 8; g++) {
            int col = col0 + wn + g * 8 + (lane & 3) * 2;
            float bx = 0.f, by = 0.f;
            if (o.bias) { bx = o.bias[col]; by = o.bias[col + 1]; }
            float v0 = acc[ti][g][0] + bx, v1 = acc[ti][g][1] + by;
            float v2 = acc[ti][g][2] + bx, v3 = acc[ti][g][3] + by;
            if (o.Chi) {
                __nv_bfloat16 h0, h1, l0, l1;
                if (rb < Nrows) {
                    split1(v0, h0, l0); split1(v1, h1, l1);
                    *(__nv_bfloat162*)&o.Chi[(long)rb * Ncols + col] = __halves2bfloat162(h0, h1);
                    *(__nv_bfloat162*)&o.Clo[(long)rb * Ncols + col] = __halves2bfloat162(l0, l1);
                }
                if (rb + 8 < Nrows) {
                    split1(v2, h0, l0); split1(v3, h1, l1);
                    *(__nv_bfloat162*)&o.Chi[(long)(rb+8) * Ncols + col] = __halves2bfloat162(h0, h1);
                    *(__nv_bfloat162*)&o.Clo[(long)(rb+8) * Ncols + col] = __halves2bfloat162(l0, l1);
                }
            } else {
                if (rb < Nrows)
                    *(float2*)&o.C[(long)rb * Ncols + col] = make_float2(v0, v1);
                if (rb + 8 < Nrows)
                    *(float2*)&o.C[(long)(rb + 8) * Ncols + col] = make_float2(v2, v3);
            }
        }
    }
}

// ============================ aggregation (4x unrolled, fused split) =========
__global__ void aggregate_split_kernel(const float4* __restrict__ h4,
                                       __nv_bfloat16* __restrict__ ahi,
                                       __nv_bfloat16* __restrict__ alo,
                                       const int* __restrict__ rowptr,
                                       const int* __restrict__ csr, int C4)
{
    int n = blockIdx.x * blockDim.y + threadIdx.y;
    if (n >= N_NODES) return;
    int f = threadIdx.x;
    int beg = rowptr[n], end = rowptr[n + 1];
    float4 a0 = make_float4(0.f,0.f,0.f,0.f), a1 = a0, a2 = a0, a3 = a0;
    int j = beg;
    for (; j + 4 <= end; j += 4) {
        int s0 = csr[j], s1 = csr[j+1], s2 = csr[j+2], s3 = csr[j+3];
        float4 v0 = h4[(long)s0 * C4 + f];
        float4 v1 = h4[(long)s1 * C4 + f];
        float4 v2 = h4[(long)s2 * C4 + f];
        float4 v3 = h4[(long)s3 * C4 + f];
        a0.x += v0.x; a0.y += v0.y; a0.z += v0.z; a0.w += v0.w;
        a1.x += v1.x; a1.y += v1.y; a1.z += v1.z; a1.w += v1.w;
        a2.x += v2.x; a2.y += v2.y; a2.z += v2.z; a2.w += v2.w;
        a3.x += v3.x; a3.y += v3.y; a3.z += v3.z; a3.w += v3.w;
    }
    for (; j < end; j++) {
        int s = csr[j];
        float4 v = h4[(long)s * C4 + f];
        a0.x += v.x; a0.y += v.y; a0.z += v.z; a0.w += v.w;
    }
    float4 acc;
    acc.x = (a0.x + a1.x) + (a2.x + a3.x);
    acc.y = (a0.y + a1.y) + (a2.y + a3.y);
    acc.z = (a0.z + a1.z) + (a2.z + a3.z);
    acc.w = (a0.w + a1.w) + (a2.w + a3.w);
    long o = ((long)n * C4 + f) * 2;
    __nv_bfloat16 h0,h1,h2,h3,l0,l1,l2,l3;
    split1(acc.x, h0, l0); split1(acc.y, h1, l1);
    split1(acc.z, h2, l2); split1(acc.w, h3, l3);
    ((__nv_bfloat162*)ahi)[o]   = __halves2bfloat162(h0, h1);
    ((__nv_bfloat162*)ahi)[o+1] = __halves2bfloat162(h2, h3);
    ((__nv_bfloat162*)alo)[o]   = __halves2bfloat162(l0, l1);
    ((__nv_bfloat162*)alo)[o+1] = __halves2bfloat162(l2, l3);
}

// ============================ GRU (float4, fused split) ======================
__global__ void gru_split_kernel(const float4* __restrict__ gi4, const float4* __restrict__ gh4,
                                 const float4* __restrict__ h4, float4* __restrict__ hout4,
                                 __nv_bfloat16* __restrict__ hhi, __nv_bfloat16* __restrict__ hlo,
                                 int C)
{
    int i = blockIdx.x * blockDim.x + threadIdx.x;
    int C4 = C >> 2;
    if (i >= N_NODES * C4) return;
    int n = i / C4, f4 = i % C4;
    const float4* gir = gi4 + (long)n * 3 * C4;
    const float4* ghr = gh4 + (long)n * 3 * C4;
    float4 ir = gir[f4], iz = gir[C4 + f4], in_ = gir[2 * C4 + f4];
    float4 hr = ghr[f4], hz = ghr[C4 + f4], hn  = ghr[2 * C4 + f4];
    float4 hv = h4[i];
    float o[4];
    {
        float r0 = 1.f / (1.f + expf(-(ir.x + hr.x)));
        float z0 = 1.f / (1.f + expf(-(iz.x + hz.x)));
        o[0] = (1.f - z0) * tanhf(in_.x + r0 * hn.x) + z0 * hv.x;
        float r1 = 1.f / (1.f + expf(-(ir.y + hr.y)));
        float z1 = 1.f / (1.f + expf(-(iz.y + hz.y)));
        o[1] = (1.f - z1) * tanhf(in_.y + r1 * hn.y) + z1 * hv.y;
        float r2 = 1.f / (1.f + expf(-(ir.z + hr.z)));
        float z2 = 1.f / (1.f + expf(-(iz.z + hz.z)));
        o[2] = (1.f - z2) * tanhf(in_.z + r2 * hn.z) + z2 * hv.z;
        float r3 = 1.f / (1.f + expf(-(ir.w + hr.w)));
        float z3 = 1.f / (1.f + expf(-(iz.w + hz.w)));
        o[3] = (1.f - z3) * tanhf(in_.w + r3 * hn.w) + z3 * hv.w;
    }
    hout4[i] = make_float4(o[0], o[1], o[2], o[3]);
    __nv_bfloat16 bh0,bh1,bh2,bh3,bl0,bl1,bl2,bl3;
    split1(o[0], bh0, bl0); split1(o[1], bh1, bl1);
    split1(o[2], bh2, bl2); split1(o[3], bh3, bl3);
    ((__nv_bfloat162*)hhi)[2*i]   = __halves2bfloat162(bh0, bh1);
    ((__nv_bfloat162*)hhi)[2*i+1] = __halves2bfloat162(bh2, bh3);
    ((__nv_bfloat162*)hlo)[2*i]   = __halves2bfloat162(bl0, bl1);
    ((__nv_bfloat162*)hlo)[2*i+1] = __halves2bfloat162(bl2, bl3);
}

__global__ void pad_relu_split_kernel(const float4* __restrict__ h1_4, float4* __restrict__ h2_4,
                                      __nv_bfloat16* __restrict__ hhi, __nv_bfloat16* __restrict__ hlo)
{
    int i = blockIdx.x * blockDim.x + threadIdx.x;
    if (i >= N_NODES * 64) return;
    int n = i >> 6, f4 = i & 63;
    float4 v = make_float4(0.f, 0.f, 0.f, 0.f);
    if (f4 < 32) {
        float4 t = h1_4[n * 32 + f4];
        v = make_float4(fmaxf(t.x, 0.f), fmaxf(t.y, 0.f), fmaxf(t.z, 0.f), fmaxf(t.w, 0.f));
    }
    h2_4[i] = v;
    __nv_bfloat16 bh0,bh1,bh2,bh3,bl0,bl1,bl2,bl3;
    split1(v.x, bh0, bl0); split1(v.y, bh1, bl1);
    split1(v.z, bh2, bl2); split1(v.w, bh3, bl3);
    ((__nv_bfloat162*)hhi)[2*i]   = __halves2bfloat162(bh0, bh1);
    ((__nv_bfloat162*)hhi)[2*i+1] = __halves2bfloat162(bh2, bh3);
    ((__nv_bfloat162*)hlo)[2*i]   = __halves2bfloat162(bl0, bl1);
    ((__nv_bfloat162*)hlo)[2*i+1] = __halves2bfloat162(bl2, bl3);
}

// ============================ pooling + FC ===================================
__global__ void pool_max_kernel(const float* __restrict__ h, const void* batch,
                                unsigned* __restrict__ pool) {
    int i = blockIdx.x * blockDim.x + threadIdx.x;
    if (i >= N_NODES * 256) return;
    int n = i >> 8, f = i & 255;
    int g = load_idx(batch, n, g_b64);
    atomicMax(&pool[g * 256 + f], f2ord(h[i]));
}
__global__ void fc_kernel(const unsigned* __restrict__ pool, const float* __restrict__ w,
                          const float* __restrict__ b, float* __restrict__ out) {
    int t = threadIdx.x;
    if (t >= N_GRAPHS * 6) return;
    int g = t / 6, j = t % 6;
    float s = b[j];
    for (int k = 0; k < 256; k++)
        s += ord2f(pool[g * 256 + k]) * w[j * 256 + k];
    out[t] = s;
}

// ============================ launch =========================================
static inline GOp mkop(const __nv_bfloat16* Ah, const __nv_bfloat16* Al,
                       const __nv_bfloat16* Bh, const __nv_bfloat16* Bl,
                       const float* bias, float* C,
                       __nv_bfloat16* Chi = nullptr, __nv_bfloat16* Clo = nullptr) {
    GOp o; o.Ah = Ah; o.Al = Al; o.Bh = Bh; o.Bl = Bl;
    o.bias = bias; o.C = C; o.Chi = Chi; o.Clo = Clo; return o;
}

extern "C" void kernel_launch(void* const* d_in, const int* in_sizes, int n_in,
                              void* d_out, int out_size)
{
    const float* x       = (const float*)d_in[0];
    const void*  edge    = d_in[1];
    const void*  batch   = d_in[2];
    const float* w1      = (const float*)d_in[3];
    const float* g1_wih  = (const float*)d_in[4];
    const float* g1_whh  = (const float*)d_in[5];
    const float* g1_bih  = (const float*)d_in[6];
    const float* g1_bhh  = (const float*)d_in[7];
    const float* w2      = (const float*)d_in[8];
    const float* g2_wih  = (const float*)d_in[9];
    const float* g2_whh  = (const float*)d_in[10];
    const float* g2_bih  = (const float*)d_in[11];
    const float* g2_bhh  = (const float*)d_in[12];
    const float* fc_w    = (const float*)d_in[13];
    const float* fc_b    = (const float*)d_in[14];

    cudaFuncSetAttribute(gemm256_kernel, cudaFuncAttributeMaxDynamicSharedMemorySize,
                         GEMM_SMEM);

    float *h1, *h2, *gi, *gh;
    int *rowptr, *cnt, *cursor, *csr;
    unsigned* pool;
    __nv_bfloat16 *hh, *hl, *ah, *al;
    __nv_bfloat16 *w1uh, *w1ul, *w2uh, *w2ul;
    __nv_bfloat16 *i1h, *i1l, *r1h, *r1l, *i2h, *i2l, *r2h, *r2l;
    __nv_bfloat16 *v1h, *v1l, *v2h, *v2l;
    cudaGetSymbolAddress((void**)&h1, g_h1);   cudaGetSymbolAddress((void**)&h2, g_h2);
    cudaGetSymbolAddress((void**)&gi, g_gi);   cudaGetSymbolAddress((void**)&gh, g_gh);
    cudaGetSymbolAddress((void**)&rowptr, g_rowptr); cudaGetSymbolAddress((void**)&cnt, g_cnt);
    cudaGetSymbolAddress((void**)&cursor, g_cursor); cudaGetSymbolAddress((void**)&csr, g_csr_src);
    cudaGetSymbolAddress((void**)&pool, g_pool);
    cudaGetSymbolAddress((void**)&hh, g_hh);   cudaGetSymbolAddress((void**)&hl, g_hl);
    cudaGetSymbolAddress((void**)&ah, g_ah);   cudaGetSymbolAddress((void**)&al, g_al);
    cudaGetSymbolAddress((void**)&w1uh, g_w1uh); cudaGetSymbolAddress((void**)&w1ul, g_w1ul);
    cudaGetSymbolAddress((void**)&w2uh, g_w2uh); cudaGetSymbolAddress((void**)&w2ul, g_w2ul);
    cudaGetSymbolAddress((void**)&i1h, g_i1h); cudaGetSymbolAddress((void**)&i1l, g_i1l);
    cudaGetSymbolAddress((void**)&r1h, g_r1h); cudaGetSymbolAddress((void**)&r1l, g_r1l);
    cudaGetSymbolAddress((void**)&i2h, g_i2h); cudaGetSymbolAddress((void**)&i2l, g_i2l);
    cudaGetSymbolAddress((void**)&r2h, g_r2h); cudaGetSymbolAddress((void**)&r2l, g_r2l);
    cudaGetSymbolAddress((void**)&v1h, g_v1h); cudaGetSymbolAddress((void**)&v1l, g_v1l);
    cudaGetSymbolAddress((void**)&v2h, g_v2h); cudaGetSymbolAddress((void**)&v2l, g_v2l);

    // 1: prep (cnt zero + pool init + dtype detect)
    prep_kernel<<<65, 256>>>(edge, batch, cnt, pool);
    // 2-4: CSR
    count_kernel<<<(N_EDGES + 255) / 256, 256>>>(edge, cnt);
    scan_kernel<<<1, 1024>>>(cnt, rowptr, cursor, N_NODES);
    fill_kernel<<<(N_EDGES + 255) / 256, 256>>>(edge, cursor, csr);

    // 5: all hi/lo splits in one launch
    SJobs js;
    js.j[0] = { x,      hh,   hl,   N_NODES*128/4 };
    js.j[1] = { w1,     w1uh, w1ul, 3*128*128/4 };
    js.j[2] = { w2,     w2uh, w2ul, 3*256*256/4 };
    js.j[3] = { g1_wih, i1h,  i1l,  384*128/4 };
    js.j[4] = { g1_whh, r1h,  r1l,  384*128/4 };
    js.j[5] = { g2_wih, i2h,  i2l,  768*256/4 };
    js.j[6] = { g2_whh, r2h,  r2l,  768*256/4 };
    split_all_kernel<<<dim3((N_NODES*128/4 + 255) / 256, 1, 7), 256>>>(js);

    // 6: first aggregation (x, fp32) — also the launch ncu profiles (-s 5 -c 1)
    aggregate_split_kernel<<<1250, dim3(32, 8)>>>((const float4*)x, ah, al, rowptr, csr, 32);

    // 7-8: V precompute, V_i = Wih @ W_i^T (bf16 hi/lo outputs)
    {
        GTriple t;
        for (int i = 0; i < 3; i++)
            t.o[i] = mkop(i1h, i1l, w1uh + (long)i*128*128, w1ul + (long)i*128*128,
                          nullptr, nullptr, v1h + (long)i*384*128, v1l + (long)i*384*128);
        gemm256_kernel<<<dim3(1, 3, 3), 256, GEMM_SMEM>>>(t, 384, 128, 128);
    }
    {
        GTriple t;
        for (int i = 0; i < 3; i++)
            t.o[i] = mkop(i2h, i2l, w2uh + (long)i*256*256, w2ul + (long)i*256*256,
                          nullptr, nullptr, v2h + (long)i*768*256, v2l + (long)i*768*256);
        gemm256_kernel<<<dim3(2, 6, 3), 256, GEMM_SMEM>>>(t, 768, 256, 256);
    }

    // ---- stage 1: C = 128 ----
    for (int i = 0; i < 3; i++) {
        const float* h = (i == 0) ? x : h1;
        if (i > 0)
            aggregate_split_kernel<<<1250, dim3(32, 8)>>>((const float4*)h, ah, al,
                                                          rowptr, csr, 32);
        GTriple t;
        t.o[0] = mkop(ah, al, v1h + (long)i*384*128, v1l + (long)i*384*128, g1_bih, gi);
        t.o[1] = mkop(hh, hl, r1h, r1l, g1_bhh, gh);
        t.o[2] = t.o[0];
        gemm256_kernel<<<dim3(3, 79, 2), 256, GEMM_SMEM>>>(t, N_NODES, 128, 384);
        gru_split_kernel<<<(N_NODES*32 + 255) / 256, 256>>>(
            (const float4*)gi, (const float4*)gh, (const float4*)h, (float4*)h1, hh, hl, 128);
    }

    pad_relu_split_kernel<<<(N_NODES*64 + 255) / 256, 256>>>(
        (const float4*)h1, (float4*)h2, hh, hl);

    // ---- stage 2: C = 256 ----
    for (int i = 0; i < 3; i++) {
        aggregate_split_kernel<<<2500, dim3(64, 4)>>>((const float4*)h2, ah, al,
                                                      rowptr, csr, 64);
        GTriple t;
        t.o[0] = mkop(ah, al, v2h + (long)i*768*256, v2l + (long)i*768*256, g2_bih, gi);
        t.o[1] = mkop(hh, hl, r2h, r2l, g2_bhh, gh);
        t.o[2] = t.o[0];
        gemm256_kernel<<<dim3(6, 79, 2), 256, GEMM_SMEM>>>(t, N_NODES, 256, 768);
        gru_split_kernel<<<(N_NODES*64 + 255) / 256, 256>>>(
            (const float4*)gi, (const float4*)gh, (const float4*)h2, (float4*)h2, hh, hl, 256);
    }

    // pooling + FC
    pool_max_kernel<<<(N_NODES*256 + 255) / 256, 256>>>(h2, batch, pool);
    fc_kernel<<<1, N_GRAPHS * 6>>>(pool, fc_w, fc_b, (float*)d_out);
}